// round 2
// baseline (speedup 1.0000x reference)
#include <cuda_runtime.h>
#include <cuda_bf16.h>
#include <math.h>

// ---------------------------------------------------------------------------
// Problem constants
// ---------------------------------------------------------------------------
#define BATCH   8
#define SEQ     256
#define DIM     1024
#define G4      4096        // 4*DIM
#define VOCAB   32000
#define ROWS    2048        // BATCH*SEQ
#define NBLK    128         // persistent LSTM grid
#define HP      1028        // padded row stride for h in smem (bank-conflict free)

// ---------------------------------------------------------------------------
// Device-global scratch (static allocation is allowed; runtime alloc is not)
// ---------------------------------------------------------------------------
__device__ float g_X[ROWS * DIM];          // embedded inputs           (8 MB)
__device__ float g_Gx0[ROWS * G4];         // precomputed x@Wx0^T + b   (32 MB)
__device__ float g_lstm_out[ROWS * DIM];   // h1 per (b,t)              (8 MB)
__device__ float g_normed[ROWS * DIM];     // rmsnormed                 (8 MB)
__device__ float g_h0[BATCH * DIM];
__device__ float g_h1[BATCH * DIM];
__device__ unsigned g_bar_count = 0;
__device__ unsigned g_bar_gen   = 0;

__device__ __forceinline__ float sigf(float x) { return 1.f / (1.f + expf(-x)); }

// ---------------------------------------------------------------------------
// Embedding gather: one block per (b,s) row, 256 threads x float4
// ---------------------------------------------------------------------------
__global__ __launch_bounds__(256) void embed_kernel(const int* __restrict__ ids,
                                                    const float* __restrict__ emb) {
    const int row = blockIdx.x;
    const int id  = ids[row];
    const float4* src = (const float4*)(emb + (size_t)id * DIM);
    float4*       dst = (float4*)(g_X + (size_t)row * DIM);
    dst[threadIdx.x] = src[threadIdx.x];
}

// ---------------------------------------------------------------------------
// SGEMM core: C[M,N] = A[M,K] * B[N,K]^T (+ bias1[n] + bias2[n])
// 128x128 block tile, BK=8, 8x8 per-thread microtile, 256 threads
// ---------------------------------------------------------------------------
__device__ __forceinline__ void sgemm_core(int M, int N, int K,
                                           const float* __restrict__ A,
                                           const float* __restrict__ B,
                                           const float* __restrict__ b1,
                                           const float* __restrict__ b2,
                                           float* __restrict__ C) {
    __shared__ __align__(16) float As[8][132];
    __shared__ __align__(16) float Bs[8][132];

    const int tid  = threadIdx.x;
    const int bRow = blockIdx.y, bCol = blockIdx.x;
    const int ldRow = tid >> 1;          // 0..127
    const int ldCol = (tid & 1) << 2;    // 0 or 4
    const float* Aptr = A + (size_t)(bRow * 128 + ldRow) * K + ldCol;
    const float* Bptr = B + (size_t)(bCol * 128 + ldRow) * K + ldCol;
    const int tRow = tid >> 4, tCol = tid & 15;

    float acc[8][8];
#pragma unroll
    for (int i = 0; i < 8; i++)
#pragma unroll
        for (int j = 0; j < 8; j++) acc[i][j] = 0.f;

    for (int k0 = 0; k0 < K; k0 += 8) {
        const float4 av = *(const float4*)(Aptr + k0);
        const float4 bv = *(const float4*)(Bptr + k0);
        As[ldCol + 0][ldRow] = av.x; As[ldCol + 1][ldRow] = av.y;
        As[ldCol + 2][ldRow] = av.z; As[ldCol + 3][ldRow] = av.w;
        Bs[ldCol + 0][ldRow] = bv.x; Bs[ldCol + 1][ldRow] = bv.y;
        Bs[ldCol + 2][ldRow] = bv.z; Bs[ldCol + 3][ldRow] = bv.w;
        __syncthreads();
#pragma unroll
        for (int kk = 0; kk < 8; kk++) {
            float rM[8], rN[8];
            *(float4*)&rM[0] = *(const float4*)&As[kk][tRow * 8];
            *(float4*)&rM[4] = *(const float4*)&As[kk][tRow * 8 + 4];
            *(float4*)&rN[0] = *(const float4*)&Bs[kk][tCol * 8];
            *(float4*)&rN[4] = *(const float4*)&Bs[kk][tCol * 8 + 4];
#pragma unroll
            for (int i = 0; i < 8; i++)
#pragma unroll
                for (int j = 0; j < 8; j++)
                    acc[i][j] = fmaf(rM[i], rN[j], acc[i][j]);
        }
        __syncthreads();
    }

#pragma unroll
    for (int i = 0; i < 8; i++) {
        const int m = bRow * 128 + tRow * 8 + i;
#pragma unroll
        for (int j = 0; j < 8; j++) {
            const int n = bCol * 128 + tCol * 8 + j;
            float bias = 0.f;
            if (b1) bias += b1[n];
            if (b2) bias += b2[n];
            C[(size_t)m * N + n] = acc[i][j] + bias;
        }
    }
}

__global__ __launch_bounds__(256) void sgemm_gx0(const float* __restrict__ Wx0,
                                                 const float* __restrict__ bx0,
                                                 const float* __restrict__ bh0) {
    sgemm_core(ROWS, G4, DIM, g_X, Wx0, bx0, bh0, g_Gx0);
}

__global__ __launch_bounds__(256) void sgemm_logits(const float* __restrict__ Wout,
                                                    float* __restrict__ out) {
    sgemm_core(ROWS, VOCAB, DIM, g_normed, Wout, nullptr, nullptr, out);
}

// ---------------------------------------------------------------------------
// Persistent LSTM recurrence kernel.
//   Grid: 128 blocks x 1024 threads (all co-resident: 1 CTA/SM by regs).
//   Warp w -> (d_local = w>>2, kq = w&3); lane -> (gate = lane>>3, b = lane&7).
//   Block owns 8 hidden units d = blockIdx.x*8 .. +7 for the whole sequence;
//   cell state c lives in registers of the kq==0, lane<8 "cell lanes".
//   Custom grid barrier: sense via monotonically increasing generation.
// ---------------------------------------------------------------------------
#define GSYNC()                                                                  \
    do {                                                                         \
        __threadfence();                                                         \
        __syncthreads();                                                         \
        if (tid == 0) {                                                          \
            ++nbar;                                                              \
            unsigned t_ = atomicAdd(&g_bar_count, 1u) + 1u;                      \
            if (t_ % NBLK == 0u) {                                               \
                atomicAdd(&g_bar_gen, 1u);                                       \
            } else {                                                             \
                while ((int)(*((volatile unsigned*)&g_bar_gen) - s_base - nbar)  \
                       < 0) { }                                                  \
            }                                                                    \
            __threadfence();                                                     \
        }                                                                        \
        __syncthreads();                                                         \
    } while (0)

__global__ __launch_bounds__(1024, 1) void lstm_kernel(
    const float* __restrict__ Wx, const float* __restrict__ bx,
    const float* __restrict__ Wh, const float* __restrict__ bh,
    float* __restrict__ d_out) {
    extern __shared__ float smem[];
    float* hA    = smem;              // 8 x HP
    float* hB    = smem + 8 * HP;     // 8 x HP
    float* gpart = smem + 16 * HP;    // [kq][dl][lane] = 4*8*32 = 1024

    const int tid  = threadIdx.x;
    const int w    = tid >> 5, lane = tid & 31;
    const int dl   = w >> 2,   kq   = w & 3;
    const int d    = (blockIdx.x << 3) + dl;
    const int gg   = lane >> 3, b = lane & 7;
    const int r    = (gg << 10) + d;

    __shared__ unsigned s_base;
    if (tid == 0) s_base = *((volatile unsigned*)&g_bar_gen);

    // zero initial hidden states (blocks 0..7 cover it)
    {
        const int i = blockIdx.x * 1024 + tid;
        if (i < BATCH * DIM) { g_h0[i] = 0.f; g_h1[i] = 0.f; }
    }
    unsigned nbar = 0;
    GSYNC();   // states zeroed + everyone has read s_base

    const bool is_cell = (kq == 0) && (lane < 8);
    float c0r = 0.f, c1r = 0.f, h0l = 0.f, h1l = 0.f;
    float bi = 0.f, bf = 0.f, bo = 0.f, bg = 0.f;
    if (is_cell) {   // layer-1 biases (layer-0 biases are folded into Gx0)
        bi = bx[G4 + d]        + bh[G4 + d];
        bf = bx[G4 + 1024 + d] + bh[G4 + 1024 + d];
        bo = bx[G4 + 2048 + d] + bh[G4 + 2048 + d];
        bg = bx[G4 + 3072 + d] + bh[G4 + 3072 + d];
    }

    const float* Wh0r = Wh + (size_t)r * DIM + (kq << 8);
    const float* Wh1r = Wh + (size_t)G4 * DIM + (size_t)r * DIM + (kq << 8);
    const float* Wx1r = Wx + (size_t)G4 * DIM + (size_t)r * DIM + (kq << 8);
    const int gidx = ((kq << 3) + dl) * 32 + lane;

    for (int t = 0; t < SEQ; ++t) {
        // ---------- layer 0: gates = Gx0[b,t] + h0_prev @ Wh0^T ----------
        for (int i = tid; i < BATCH * DIM; i += 1024)
            hA[(i >> 10) * HP + (i & 1023)] = __ldcg(&g_h0[i]);
        __syncthreads();
        {
            float acc = 0.f;
            const float* hrow = hA + b * HP + (kq << 8);
#pragma unroll 8
            for (int kk = 0; kk < 256; kk += 4) {
                const float4 wv = *(const float4*)(Wh0r + kk);
                const float4 hv = *(const float4*)(hrow + kk);
                acc = fmaf(wv.x, hv.x, acc);
                acc = fmaf(wv.y, hv.y, acc);
                acc = fmaf(wv.z, hv.z, acc);
                acc = fmaf(wv.w, hv.w, acc);
            }
            gpart[gidx] = acc;
        }
        __syncthreads();
        if (is_cell) {
            float gate[4];
#pragma unroll
            for (int q = 0; q < 4; ++q) {
                float v = gpart[(0 * 8 + dl) * 32 + (q << 3) + lane]
                        + gpart[(1 * 8 + dl) * 32 + (q << 3) + lane]
                        + gpart[(2 * 8 + dl) * 32 + (q << 3) + lane]
                        + gpart[(3 * 8 + dl) * 32 + (q << 3) + lane];
                gate[q] = v + g_Gx0[(size_t)((lane << 8) + t) * G4 + (q << 10) + d];
            }
            const float ct = sigf(gate[1]) * c0r + sigf(gate[0]) * tanhf(gate[3]);
            const float ht = sigf(gate[2]) * tanhf(ct);
            c0r = ct; h0l = ht;
            g_h0[(lane << 10) + d] = ht;
        }
        GSYNC();   // h0_t visible everywhere

        // ---------- layer 1: gates = h0_t @ Wx1^T + h1_prev @ Wh1^T + b ----------
        for (int i = tid; i < BATCH * DIM; i += 1024) {
            hA[(i >> 10) * HP + (i & 1023)] = __ldcg(&g_h0[i]);
            hB[(i >> 10) * HP + (i & 1023)] = __ldcg(&g_h1[i]);
        }
        __syncthreads();
        {
            float acc = 0.f;
            const float* h0row = hA + b * HP + (kq << 8);
            const float* h1row = hB + b * HP + (kq << 8);
#pragma unroll 4
            for (int kk = 0; kk < 256; kk += 4) {
                const float4 xv = *(const float4*)(Wx1r + kk);
                const float4 av = *(const float4*)(h0row + kk);
                const float4 wv = *(const float4*)(Wh1r + kk);
                const float4 bv = *(const float4*)(h1row + kk);
                acc = fmaf(xv.x, av.x, acc);
                acc = fmaf(xv.y, av.y, acc);
                acc = fmaf(xv.z, av.z, acc);
                acc = fmaf(xv.w, av.w, acc);
                acc = fmaf(wv.x, bv.x, acc);
                acc = fmaf(wv.y, bv.y, acc);
                acc = fmaf(wv.z, bv.z, acc);
                acc = fmaf(wv.w, bv.w, acc);
            }
            gpart[gidx] = acc;
        }
        __syncthreads();
        if (is_cell) {
            float gate[4];
#pragma unroll
            for (int q = 0; q < 4; ++q) {
                gate[q] = gpart[(0 * 8 + dl) * 32 + (q << 3) + lane]
                        + gpart[(1 * 8 + dl) * 32 + (q << 3) + lane]
                        + gpart[(2 * 8 + dl) * 32 + (q << 3) + lane]
                        + gpart[(3 * 8 + dl) * 32 + (q << 3) + lane];
            }
            gate[0] += bi; gate[1] += bf; gate[2] += bo; gate[3] += bg;
            const float ct = sigf(gate[1]) * c1r + sigf(gate[0]) * tanhf(gate[3]);
            const float ht = sigf(gate[2]) * tanhf(ct);
            c1r = ct; h1l = ht;
            g_h1[(lane << 10) + d] = ht;
            g_lstm_out[(size_t)((lane << 8) + t) * DIM + d] = ht;
        }
        GSYNC();   // h1_t visible for next step
    }

    // final states: d_out layout = [logits | h_n (L,B,D) | c_n (L,B,D)]
    if (is_cell) {
        const size_t LOGN = (size_t)ROWS * VOCAB;
        d_out[LOGN + (lane << 10) + d]                 = h0l;
        d_out[LOGN + BATCH * DIM + (lane << 10) + d]   = h1l;
        d_out[LOGN + 2 * BATCH * DIM + (lane << 10) + d]     = c0r;
        d_out[LOGN + 3 * BATCH * DIM + (lane << 10) + d]     = c1r;
    }
}

// ---------------------------------------------------------------------------
// RMSNorm (fp32): one block per row
// ---------------------------------------------------------------------------
__global__ __launch_bounds__(256) void rmsnorm_kernel(const float* __restrict__ w) {
    const int row = blockIdx.x, tid = threadIdx.x;
    const float4 v = *(((const float4*)(g_lstm_out + (size_t)row * DIM)) + tid);
    float ss = v.x * v.x + v.y * v.y + v.z * v.z + v.w * v.w;
#pragma unroll
    for (int o = 16; o; o >>= 1) ss += __shfl_xor_sync(0xffffffffu, ss, o);
    __shared__ float sred[8];
    __shared__ float sinv;
    if ((tid & 31) == 0) sred[tid >> 5] = ss;
    __syncthreads();
    if (tid == 0) {
        float tot = 0.f;
#pragma unroll
        for (int i = 0; i < 8; i++) tot += sred[i];
        sinv = rsqrtf(tot * (1.f / 1024.f) + 1e-5f);
    }
    __syncthreads();
    const float inv = sinv;
    const float4 wv = ((const float4*)w)[tid];
    float4 o4;
    o4.x = v.x * inv * wv.x;
    o4.y = v.y * inv * wv.y;
    o4.z = v.z * inv * wv.z;
    o4.w = v.w * inv * wv.w;
    *(((float4*)(g_normed + (size_t)row * DIM)) + tid) = o4;
}

// ---------------------------------------------------------------------------
// Launch
// ---------------------------------------------------------------------------
#define LSTM_SMEM_BYTES ((16 * HP + 1024) * 4)

extern "C" void kernel_launch(void* const* d_in, const int* in_sizes, int n_in,
                              void* d_out, int out_size) {
    (void)in_sizes; (void)n_in; (void)out_size;
    const int*   ids  = (const int*)d_in[0];
    const float* emb  = (const float*)d_in[1];
    const float* Wx   = (const float*)d_in[2];
    const float* bx   = (const float*)d_in[3];
    const float* Wh   = (const float*)d_in[4];
    const float* bh   = (const float*)d_in[5];
    const float* nw   = (const float*)d_in[6];
    const float* Wout = (const float*)d_in[7];
    float* out = (float*)d_out;

    cudaFuncSetAttribute(lstm_kernel, cudaFuncAttributeMaxDynamicSharedMemorySize,
                         LSTM_SMEM_BYTES);

    embed_kernel<<<ROWS, 256>>>(ids, emb);
    sgemm_gx0<<<dim3(G4 / 128, ROWS / 128), 256>>>(Wx, bx, bh);
    lstm_kernel<<<NBLK, 1024, LSTM_SMEM_BYTES>>>(Wx, bx, Wh, bh, out);
    rmsnorm_kernel<<<ROWS, 256>>>(nw);
    sgemm_logits<<<dim3(VOCAB / 128, ROWS / 128), 256>>>(Wout, out);
}

// round 10
// speedup vs baseline: 1.2312x; 1.2312x over previous
#include <cuda_runtime.h>
#include <cuda_bf16.h>
#include <math.h>
#include <cstdint>

// ---------------------------------------------------------------------------
// Problem constants
// ---------------------------------------------------------------------------
#define BATCH   8
#define SEQ     256
#define DIM     1024
#define G4      4096        // 4*DIM
#define VOCAB   32000
#define ROWS    2048        // BATCH*SEQ
#define NBLK    128         // persistent LSTM grid
#define HP      1028        // padded row stride for h in smem

// ---------------------------------------------------------------------------
// Device-global scratch (NEVER passed from host code — device-side refs only)
// ---------------------------------------------------------------------------
__device__ __align__(256) float g_X[ROWS * DIM];
__device__ __align__(256) float g_Gx0[ROWS * G4];
__device__ __align__(256) float g_lstm_out[ROWS * DIM];
__device__ __align__(256) float g_normed[ROWS * DIM];
__device__ __align__(256) float g_h0[BATCH * DIM];
__device__ __align__(256) float g_h1[BATCH * DIM];
__device__ unsigned g_bar_count = 0;
__device__ unsigned g_bar_gen   = 0;

// split-bf16 operands
__device__ __align__(256) __nv_bfloat16 g_Ahi[ROWS * DIM],   g_Alo[ROWS * DIM];
__device__ __align__(256) __nv_bfloat16 g_Wxhi[G4 * DIM],    g_Wxlo[G4 * DIM];
__device__ __align__(256) __nv_bfloat16 g_Wohi[VOCAB * DIM], g_Wolo[VOCAB * DIM];

__device__ __forceinline__ float sigf(float x) { return 1.f / (1.f + expf(-x)); }

__device__ __forceinline__ uint32_t smem_to_u32(const void* p) {
    uint32_t a;
    asm("{ .reg .u64 t; cvta.to.shared.u64 t, %1; cvt.u32.u64 %0, t; }"
        : "=r"(a) : "l"(p));
    return a;
}
__device__ __forceinline__ void cpa16(uint32_t dst, const void* src) {
    asm volatile("cp.async.cg.shared.global [%0], [%1], 16;"
                 :: "r"(dst), "l"(src));
}
__device__ __forceinline__ void ldsm4(uint32_t* r, uint32_t addr) {
    asm volatile("ldmatrix.sync.aligned.m8n8.x4.shared.b16 {%0,%1,%2,%3}, [%4];"
                 : "=r"(r[0]), "=r"(r[1]), "=r"(r[2]), "=r"(r[3]) : "r"(addr));
}
__device__ __forceinline__ void mma16816(float* d, const uint32_t* a,
                                         const uint32_t* b) {
    asm volatile(
        "mma.sync.aligned.m16n8k16.row.col.f32.bf16.bf16.f32 "
        "{%0,%1,%2,%3},{%4,%5,%6,%7},{%8,%9},{%0,%1,%2,%3};"
        : "+f"(d[0]), "+f"(d[1]), "+f"(d[2]), "+f"(d[3])
        : "r"(a[0]), "r"(a[1]), "r"(a[2]), "r"(a[3]), "r"(b[0]), "r"(b[1]));
}

// ---------------------------------------------------------------------------
// Embedding gather (writes g_X device-side)
// ---------------------------------------------------------------------------
__global__ __launch_bounds__(256) void embed_kernel(const int* __restrict__ ids,
                                                    const float* __restrict__ emb) {
    const int row = blockIdx.x;
    const int id  = ids[row];
    const float4* src = (const float4*)(emb + (size_t)id * DIM);
    float4*       dst = (float4*)(g_X + (size_t)row * DIM);
    dst[threadIdx.x] = src[threadIdx.x];
}

// ---------------------------------------------------------------------------
// fp32 -> (hi, lo) bf16 split.  mode selects src/dst INSIDE device code:
//   0: g_X      -> g_Ahi/g_Alo
//   1: src_prm  -> g_Wxhi/g_Wxlo   (layer-0 Wx, harness ptr)
//   2: src_prm  -> g_Wohi/g_Wolo   (out_weight, harness ptr)
//   3: g_normed -> g_Ahi/g_Alo
// ---------------------------------------------------------------------------
__global__ __launch_bounds__(256) void convert_hilo(const float* __restrict__ src_prm,
                                                    int mode, int n) {
    const float* src = (mode == 0) ? g_X : (mode == 3) ? g_normed : src_prm;
    __nv_bfloat16 *hi, *lo;
    if (mode == 1)      { hi = g_Wxhi; lo = g_Wxlo; }
    else if (mode == 2) { hi = g_Wohi; lo = g_Wolo; }
    else                { hi = g_Ahi;  lo = g_Alo;  }
    int i = blockIdx.x * blockDim.x + threadIdx.x;
    const int stride = gridDim.x * blockDim.x;
    for (; i < n; i += stride) {
        const float x = src[i];
        const __nv_bfloat16 h = __float2bfloat16_rn(x);
        hi[i] = h;
        lo[i] = __float2bfloat16_rn(x - __bfloat162float(h));
    }
}

// ---------------------------------------------------------------------------
// Split-bf16 HMMA GEMM: C[M,N] = A[M,1024] * B[N,1024]^T (+bias1+bias2)
//   acc = Ahi*Bhi + Ahi*Blo + Alo*Bhi  (fp32 accum via mma.sync m16n8k16)
//   CTA 128x128, K chunk 32, double-buffered cp.async, 8 warps (4x2).
//   mode 0: B = g_Wx(hi/lo),  C = g_Gx0,  N = G4,    bias = bx0+bh0
//   mode 1: B = g_Wo(hi/lo),  C = outC,   N = VOCAB, no bias
// ---------------------------------------------------------------------------
#define OPD_B   8192                 // 128 rows * 32 halves * 2B
#define STAGE_B (4 * OPD_B)          // Ahi|Alo|Bhi|Blo
#define GEMM_SMEM_BYTES (2 * STAGE_B)
#define NSTAGE  (DIM / 32)           // 32

__global__ __launch_bounds__(256) void gemm3_mma(
    int mode, const float* __restrict__ bias1, const float* __restrict__ bias2,
    float* __restrict__ outC) {
    const __nv_bfloat16* __restrict__ Ahi = g_Ahi;
    const __nv_bfloat16* __restrict__ Alo = g_Alo;
    const __nv_bfloat16* __restrict__ Bhi = mode ? g_Wohi : g_Wxhi;
    const __nv_bfloat16* __restrict__ Blo = mode ? g_Wolo : g_Wxlo;
    float* __restrict__ C = mode ? outC : g_Gx0;
    const int N = mode ? VOCAB : G4;

    extern __shared__ __align__(128) char smem[];
    const uint32_t sbase = smem_to_u32(smem);
    const int tid  = threadIdx.x;
    const int lane = tid & 31;
    const int warp = tid >> 5;
    const int wm   = warp & 3;           // 0..3 -> 32-row slice
    const int wn   = warp >> 2;          // 0..1 -> 64-col slice
    const int mTile = blockIdx.y * 128;
    const int nTile = blockIdx.x * 128;

    // ---- global-load geometry: 2 threads/row, 2x16B chunks each ----
    const int gRow  = tid >> 1;          // 0..127
    const int cBase = (tid & 1) * 2;     // 16B chunk index base (of 4 per row)
    uint32_t sOff[2];
#pragma unroll
    for (int j = 0; j < 2; ++j) {
        const int c = cBase + j;
        sOff[j] = gRow * 64 + ((c ^ (gRow & 3)) << 4);   // XOR swizzle
    }
    const __nv_bfloat16* pAh = Ahi + (size_t)(mTile + gRow) * DIM;
    const __nv_bfloat16* pAl = Alo + (size_t)(mTile + gRow) * DIM;
    const __nv_bfloat16* pBh = Bhi + (size_t)(nTile + gRow) * DIM;
    const __nv_bfloat16* pBl = Blo + (size_t)(nTile + gRow) * DIM;

#define PREFETCH(s)                                                            \
    do {                                                                       \
        const uint32_t db = sbase + ((s) & 1) * STAGE_B;                       \
        const int k0 = (s) * 32;                                               \
        _Pragma("unroll")                                                      \
        for (int j = 0; j < 2; ++j) {                                          \
            const int kh = k0 + (cBase + j) * 8;                               \
            cpa16(db + 0 * OPD_B + sOff[j], pAh + kh);                         \
            cpa16(db + 1 * OPD_B + sOff[j], pAl + kh);                         \
            cpa16(db + 2 * OPD_B + sOff[j], pBh + kh);                         \
            cpa16(db + 3 * OPD_B + sOff[j], pBl + kh);                         \
        }                                                                      \
        asm volatile("cp.async.commit_group;");                                \
    } while (0)

    float acc[2][8][4];
#pragma unroll
    for (int i = 0; i < 2; ++i)
#pragma unroll
        for (int j = 0; j < 8; ++j)
#pragma unroll
            for (int k = 0; k < 4; ++k) acc[i][j][k] = 0.f;

    PREFETCH(0);

    // ldmatrix lane geometry
    const int aRowB = wm * 32 + (lane & 7) + ((lane >> 3) & 1) * 8;
    const int bRowB = wn * 64 + (lane & 7) + ((lane >> 4) & 1) * 8;
    const int aCsel = (lane >> 4) & 1;
    const int bCsel = (lane >> 3) & 1;

    for (int s = 0; s < NSTAGE; ++s) {
        if (s + 1 < NSTAGE) {
            PREFETCH(s + 1);
            asm volatile("cp.async.wait_group 1;");
        } else {
            asm volatile("cp.async.wait_group 0;");
        }
        __syncthreads();

        const uint32_t sa = sbase + (s & 1) * STAGE_B;
#pragma unroll
        for (int ks = 0; ks < 2; ++ks) {
            uint32_t aHi[2][4], aLo[2][4], bHi[8][2], bLo[8][2];
            const int cA = ks * 2 + aCsel;
            const int cB = ks * 2 + bCsel;
#pragma unroll
            for (int mt = 0; mt < 2; ++mt) {
                const int r_ = aRowB + mt * 16;
                const uint32_t off = r_ * 64 + ((cA ^ (r_ & 3)) << 4);
                ldsm4(aHi[mt], sa + off);
                ldsm4(aLo[mt], sa + OPD_B + off);
            }
#pragma unroll
            for (int p = 0; p < 4; ++p) {
                const int r_ = bRowB + p * 16;
                const uint32_t off = r_ * 64 + ((cB ^ (r_ & 3)) << 4);
                ldsm4(&bHi[2 * p][0], sa + 2 * OPD_B + off);
                ldsm4(&bLo[2 * p][0], sa + 3 * OPD_B + off);
            }
#pragma unroll
            for (int mt = 0; mt < 2; ++mt)
#pragma unroll
                for (int nt = 0; nt < 8; ++nt) {
                    mma16816(acc[mt][nt], aHi[mt], bHi[nt]);
                    mma16816(acc[mt][nt], aHi[mt], bLo[nt]);
                    mma16816(acc[mt][nt], aLo[mt], bHi[nt]);
                }
        }
        __syncthreads();
    }

    // ---- epilogue ----
    const int mBaseW = mTile + wm * 32 + (lane >> 2);
    const int nBaseW = nTile + wn * 64 + (lane & 3) * 2;
#pragma unroll
    for (int mt = 0; mt < 2; ++mt)
#pragma unroll
        for (int nt = 0; nt < 8; ++nt) {
            const int n = nBaseW + nt * 8;
            float b0 = 0.f, b1 = 0.f;
            if (mode == 0) {
                b0 = bias1[n] + bias2[n];
                b1 = bias1[n + 1] + bias2[n + 1];
            }
            const int m0 = mBaseW + mt * 16;
            float2 v0 = make_float2(acc[mt][nt][0] + b0, acc[mt][nt][1] + b1);
            float2 v1 = make_float2(acc[mt][nt][2] + b0, acc[mt][nt][3] + b1);
            *(float2*)(C + (size_t)m0 * N + n)       = v0;
            *(float2*)(C + (size_t)(m0 + 8) * N + n) = v1;
        }
#undef PREFETCH
}

// ---------------------------------------------------------------------------
// Persistent LSTM recurrence kernel (unchanged — passed in Round 1/2)
// ---------------------------------------------------------------------------
#define GSYNC()                                                                  \
    do {                                                                         \
        __threadfence();                                                         \
        __syncthreads();                                                         \
        if (tid == 0) {                                                          \
            ++nbar;                                                              \
            unsigned t_ = atomicAdd(&g_bar_count, 1u) + 1u;                      \
            if (t_ % NBLK == 0u) {                                               \
                atomicAdd(&g_bar_gen, 1u);                                       \
            } else {                                                             \
                while ((int)(*((volatile unsigned*)&g_bar_gen) - s_base - nbar)  \
                       < 0) { }                                                  \
            }                                                                    \
            __threadfence();                                                     \
        }                                                                        \
        __syncthreads();                                                         \
    } while (0)

__global__ __launch_bounds__(1024, 1) void lstm_kernel(
    const float* __restrict__ Wx, const float* __restrict__ bx,
    const float* __restrict__ Wh, const float* __restrict__ bh,
    float* __restrict__ d_out) {
    extern __shared__ float smemf[];
    float* hA    = smemf;
    float* hB    = smemf + 8 * HP;
    float* gpart = smemf + 16 * HP;

    const int tid  = threadIdx.x;
    const int w    = tid >> 5, lane = tid & 31;
    const int dl   = w >> 2,   kq   = w & 3;
    const int d    = (blockIdx.x << 3) + dl;
    const int gg   = lane >> 3, b = lane & 7;
    const int r    = (gg << 10) + d;

    __shared__ unsigned s_base;
    if (tid == 0) s_base = *((volatile unsigned*)&g_bar_gen);

    {
        const int i = blockIdx.x * 1024 + tid;
        if (i < BATCH * DIM) { g_h0[i] = 0.f; g_h1[i] = 0.f; }
    }
    unsigned nbar = 0;
    GSYNC();

    const bool is_cell = (kq == 0) && (lane < 8);
    float c0r = 0.f, c1r = 0.f, h0l = 0.f, h1l = 0.f;
    float bi = 0.f, bf = 0.f, bo = 0.f, bg = 0.f;
    if (is_cell) {
        bi = bx[G4 + d]        + bh[G4 + d];
        bf = bx[G4 + 1024 + d] + bh[G4 + 1024 + d];
        bo = bx[G4 + 2048 + d] + bh[G4 + 2048 + d];
        bg = bx[G4 + 3072 + d] + bh[G4 + 3072 + d];
    }

    const float* Wh0r = Wh + (size_t)r * DIM + (kq << 8);
    const float* Wh1r = Wh + (size_t)G4 * DIM + (size_t)r * DIM + (kq << 8);
    const float* Wx1r = Wx + (size_t)G4 * DIM + (size_t)r * DIM + (kq << 8);
    const int gidx = ((kq << 3) + dl) * 32 + lane;

    for (int t = 0; t < SEQ; ++t) {
        for (int i = tid; i < BATCH * DIM; i += 1024)
            hA[(i >> 10) * HP + (i & 1023)] = __ldcg(&g_h0[i]);
        __syncthreads();
        {
            float acc = 0.f;
            const float* hrow = hA + b * HP + (kq << 8);
#pragma unroll 8
            for (int kk = 0; kk < 256; kk += 4) {
                const float4 wv = *(const float4*)(Wh0r + kk);
                const float4 hv = *(const float4*)(hrow + kk);
                acc = fmaf(wv.x, hv.x, acc);
                acc = fmaf(wv.y, hv.y, acc);
                acc = fmaf(wv.z, hv.z, acc);
                acc = fmaf(wv.w, hv.w, acc);
            }
            gpart[gidx] = acc;
        }
        __syncthreads();
        if (is_cell) {
            float gate[4];
#pragma unroll
            for (int q = 0; q < 4; ++q) {
                float v = gpart[(0 * 8 + dl) * 32 + (q << 3) + lane]
                        + gpart[(1 * 8 + dl) * 32 + (q << 3) + lane]
                        + gpart[(2 * 8 + dl) * 32 + (q << 3) + lane]
                        + gpart[(3 * 8 + dl) * 32 + (q << 3) + lane];
                gate[q] = v + g_Gx0[(size_t)((lane << 8) + t) * G4 + (q << 10) + d];
            }
            const float ct = sigf(gate[1]) * c0r + sigf(gate[0]) * tanhf(gate[3]);
            const float ht = sigf(gate[2]) * tanhf(ct);
            c0r = ct; h0l = ht;
            g_h0[(lane << 10) + d] = ht;
        }
        GSYNC();

        for (int i = tid; i < BATCH * DIM; i += 1024) {
            hA[(i >> 10) * HP + (i & 1023)] = __ldcg(&g_h0[i]);
            hB[(i >> 10) * HP + (i & 1023)] = __ldcg(&g_h1[i]);
        }
        __syncthreads();
        {
            float acc = 0.f;
            const float* h0row = hA + b * HP + (kq << 8);
            const float* h1row = hB + b * HP + (kq << 8);
#pragma unroll 4
            for (int kk = 0; kk < 256; kk += 4) {
                const float4 xv = *(const float4*)(Wx1r + kk);
                const float4 av = *(const float4*)(h0row + kk);
                const float4 wv = *(const float4*)(Wh1r + kk);
                const float4 bv = *(const float4*)(h1row + kk);
                acc = fmaf(xv.x, av.x, acc);
                acc = fmaf(xv.y, av.y, acc);
                acc = fmaf(xv.z, av.z, acc);
                acc = fmaf(xv.w, av.w, acc);
                acc = fmaf(wv.x, bv.x, acc);
                acc = fmaf(wv.y, bv.y, acc);
                acc = fmaf(wv.z, bv.z, acc);
                acc = fmaf(wv.w, bv.w, acc);
            }
            gpart[gidx] = acc;
        }
        __syncthreads();
        if (is_cell) {
            float gate[4];
#pragma unroll
            for (int q = 0; q < 4; ++q) {
                gate[q] = gpart[(0 * 8 + dl) * 32 + (q << 3) + lane]
                        + gpart[(1 * 8 + dl) * 32 + (q << 3) + lane]
                        + gpart[(2 * 8 + dl) * 32 + (q << 3) + lane]
                        + gpart[(3 * 8 + dl) * 32 + (q << 3) + lane];
            }
            gate[0] += bi; gate[1] += bf; gate[2] += bo; gate[3] += bg;
            const float ct = sigf(gate[1]) * c1r + sigf(gate[0]) * tanhf(gate[3]);
            const float ht = sigf(gate[2]) * tanhf(ct);
            c1r = ct; h1l = ht;
            g_h1[(lane << 10) + d] = ht;
            g_lstm_out[(size_t)((lane << 8) + t) * DIM + d] = ht;
        }
        GSYNC();
    }

    if (is_cell) {
        const size_t LOGN = (size_t)ROWS * VOCAB;
        d_out[LOGN + (lane << 10) + d]                   = h0l;
        d_out[LOGN + BATCH * DIM + (lane << 10) + d]     = h1l;
        d_out[LOGN + 2 * BATCH * DIM + (lane << 10) + d] = c0r;
        d_out[LOGN + 3 * BATCH * DIM + (lane << 10) + d] = c1r;
    }
}

// ---------------------------------------------------------------------------
// RMSNorm (fp32)
// ---------------------------------------------------------------------------
__global__ __launch_bounds__(256) void rmsnorm_kernel(const float* __restrict__ w) {
    const int row = blockIdx.x, tid = threadIdx.x;
    const float4 v = *(((const float4*)(g_lstm_out + (size_t)row * DIM)) + tid);
    float ss = v.x * v.x + v.y * v.y + v.z * v.z + v.w * v.w;
#pragma unroll
    for (int o = 16; o; o >>= 1) ss += __shfl_xor_sync(0xffffffffu, ss, o);
    __shared__ float sred[8];
    __shared__ float sinv;
    if ((tid & 31) == 0) sred[tid >> 5] = ss;
    __syncthreads();
    if (tid == 0) {
        float tot = 0.f;
#pragma unroll
        for (int i = 0; i < 8; i++) tot += sred[i];
        sinv = rsqrtf(tot * (1.f / 1024.f) + 1e-5f);
    }
    __syncthreads();
    const float inv = sinv;
    const float4 wv = ((const float4*)w)[tid];
    float4 o4;
    o4.x = v.x * inv * wv.x;
    o4.y = v.y * inv * wv.y;
    o4.z = v.z * inv * wv.z;
    o4.w = v.w * inv * wv.w;
    *(((float4*)(g_normed + (size_t)row * DIM)) + tid) = o4;
}

// ---------------------------------------------------------------------------
// Launch — only harness pointers cross the host/device boundary
// ---------------------------------------------------------------------------
#define LSTM_SMEM_BYTES ((16 * HP + 1024) * 4)

extern "C" void kernel_launch(void* const* d_in, const int* in_sizes, int n_in,
                              void* d_out, int out_size) {
    (void)in_sizes; (void)n_in; (void)out_size;
    const int*   ids  = (const int*)d_in[0];
    const float* emb  = (const float*)d_in[1];
    const float* Wx   = (const float*)d_in[2];
    const float* bx   = (const float*)d_in[3];
    const float* Wh   = (const float*)d_in[4];
    const float* bh   = (const float*)d_in[5];
    const float* nw   = (const float*)d_in[6];
    const float* Wout = (const float*)d_in[7];
    float* out = (float*)d_out;

    cudaFuncSetAttribute(lstm_kernel, cudaFuncAttributeMaxDynamicSharedMemorySize,
                         LSTM_SMEM_BYTES);
    cudaFuncSetAttribute(gemm3_mma, cudaFuncAttributeMaxDynamicSharedMemorySize,
                         GEMM_SMEM_BYTES);

    embed_kernel<<<ROWS, 256>>>(ids, emb);
    convert_hilo<<<2048, 256>>>(nullptr, 0, ROWS * DIM);     // g_X -> g_Ahi/lo
    convert_hilo<<<2048, 256>>>(Wx,      1, G4 * DIM);       // Wx0 -> g_Wxhi/lo
    convert_hilo<<<4096, 256>>>(Wout,    2, VOCAB * DIM);    // Wout -> g_Wohi/lo

    // Gx0 = X @ Wx0^T + bx0 + bh0
    gemm3_mma<<<dim3(G4 / 128, ROWS / 128), 256, GEMM_SMEM_BYTES>>>(0, bx, bh, out);

    lstm_kernel<<<NBLK, 1024, LSTM_SMEM_BYTES>>>(Wx, bx, Wh, bh, out);
    rmsnorm_kernel<<<ROWS, 256>>>(nw);

    convert_hilo<<<2048, 256>>>(nullptr, 3, ROWS * DIM);     // g_normed -> g_Ahi/lo

    // logits = normed @ Wout^T
    gemm3_mma<<<dim3(VOCAB / 128, ROWS / 128), 256, GEMM_SMEM_BYTES>>>(
        1, nullptr, nullptr, out);
}

// round 12
// speedup vs baseline: 1.2315x; 1.0002x over previous
#include <cuda_runtime.h>
#include <cuda_bf16.h>
#include <math.h>
#include <cstdint>

// ---------------------------------------------------------------------------
// Problem constants
// ---------------------------------------------------------------------------
#define BATCH   8
#define SEQ     256
#define DIM     1024
#define G4      4096        // 4*DIM
#define VOCAB   32000
#define ROWS    2048        // BATCH*SEQ
#define NBLK    128         // persistent LSTM grid
#define HP      1028        // padded row stride for h in smem
#define WP      1028        // padded row stride for cached weights

// ---------------------------------------------------------------------------
// Device-global scratch (device-side references only — never host args)
// ---------------------------------------------------------------------------
__device__ __align__(256) float g_Gx0[ROWS * G4];
__device__ __align__(256) float g_lstm_out[ROWS * DIM];
__device__ __align__(256) float g_normed[ROWS * DIM];
__device__ __align__(256) float g_h0[BATCH * DIM];
__device__ __align__(256) float g_h1[BATCH * DIM];
__device__ unsigned g_bar_count = 0;
__device__ unsigned g_bar_gen   = 0;

// split-bf16 operands
__device__ __align__(256) __nv_bfloat16 g_Ahi[ROWS * DIM],   g_Alo[ROWS * DIM];
__device__ __align__(256) __nv_bfloat16 g_Wxhi[G4 * DIM],    g_Wxlo[G4 * DIM];
__device__ __align__(256) __nv_bfloat16 g_Wohi[VOCAB * DIM], g_Wolo[VOCAB * DIM];

__device__ __forceinline__ float sigf(float x) { return 1.f / (1.f + expf(-x)); }

__device__ __forceinline__ uint32_t smem_to_u32(const void* p) {
    uint32_t a;
    asm("{ .reg .u64 t; cvta.to.shared.u64 t, %1; cvt.u32.u64 %0, t; }"
        : "=r"(a) : "l"(p));
    return a;
}
__device__ __forceinline__ void cpa16(uint32_t dst, const void* src) {
    asm volatile("cp.async.cg.shared.global [%0], [%1], 16;"
                 :: "r"(dst), "l"(src));
}
__device__ __forceinline__ void ldsm4(uint32_t* r, uint32_t addr) {
    asm volatile("ldmatrix.sync.aligned.m8n8.x4.shared.b16 {%0,%1,%2,%3}, [%4];"
                 : "=r"(r[0]), "=r"(r[1]), "=r"(r[2]), "=r"(r[3]) : "r"(addr));
}
__device__ __forceinline__ void mma16816(float* d, const uint32_t* a,
                                         const uint32_t* b) {
    asm volatile(
        "mma.sync.aligned.m16n8k16.row.col.f32.bf16.bf16.f32 "
        "{%0,%1,%2,%3},{%4,%5,%6,%7},{%8,%9},{%0,%1,%2,%3};"
        : "+f"(d[0]), "+f"(d[1]), "+f"(d[2]), "+f"(d[3])
        : "r"(a[0]), "r"(a[1]), "r"(a[2]), "r"(a[3]), "r"(b[0]), "r"(b[1]));
}

// ---------------------------------------------------------------------------
// Embedding gather fused with hi/lo bf16 split (launch index 0)
// ---------------------------------------------------------------------------
__global__ __launch_bounds__(256) void embed_split_kernel(
    const int* __restrict__ ids, const float* __restrict__ emb) {
    const int row = blockIdx.x;
    const int id  = ids[row];
    const float4 v = ((const float4*)(emb + (size_t)id * DIM))[threadIdx.x];
    const size_t base = (size_t)row * DIM + threadIdx.x * 4;
    __nv_bfloat162* hi2 = (__nv_bfloat162*)(g_Ahi + base);
    __nv_bfloat162* lo2 = (__nv_bfloat162*)(g_Alo + base);
    __nv_bfloat162 h0 = __floats2bfloat162_rn(v.x, v.y);
    __nv_bfloat162 h1 = __floats2bfloat162_rn(v.z, v.w);
    hi2[0] = h0;
    hi2[1] = h1;
    lo2[0] = __floats2bfloat162_rn(v.x - __bfloat162float(__low2bfloat16(h0)),
                                   v.y - __bfloat162float(__high2bfloat16(h0)));
    lo2[1] = __floats2bfloat162_rn(v.z - __bfloat162float(__low2bfloat16(h1)),
                                   v.w - __bfloat162float(__high2bfloat16(h1)));
}

// ---------------------------------------------------------------------------
// Both weight matrices -> hi/lo bf16 in ONE launch (index 1)
// ---------------------------------------------------------------------------
#define NWX (G4 * DIM)
#define NWO (VOCAB * DIM)
__global__ __launch_bounds__(256) void convertW_kernel(
    const float* __restrict__ Wx, const float* __restrict__ Wout) {
    int i = blockIdx.x * blockDim.x + threadIdx.x;
    const int stride = gridDim.x * blockDim.x;
    for (; i < NWX + NWO; i += stride) {
        float x;
        __nv_bfloat16 *hip, *lop;
        if (i < NWX) {
            x = Wx[i]; hip = g_Wxhi + i; lop = g_Wxlo + i;
        } else {
            const int j = i - NWX;
            x = Wout[j]; hip = g_Wohi + j; lop = g_Wolo + j;
        }
        const __nv_bfloat16 h = __float2bfloat16_rn(x);
        *hip = h;
        *lop = __float2bfloat16_rn(x - __bfloat162float(h));
    }
}

// ---------------------------------------------------------------------------
// normed -> hi/lo bf16 (launch index 5)
// ---------------------------------------------------------------------------
__global__ __launch_bounds__(256) void conv_normed_kernel() {
    int i = blockIdx.x * blockDim.x + threadIdx.x;
    const int stride = gridDim.x * blockDim.x;
    for (; i < ROWS * DIM; i += stride) {
        const float x = g_normed[i];
        const __nv_bfloat16 h = __float2bfloat16_rn(x);
        g_Ahi[i] = h;
        g_Alo[i] = __float2bfloat16_rn(x - __bfloat162float(h));
    }
}

// ---------------------------------------------------------------------------
// Split-bf16 HMMA GEMM: C[M,N] = A[M,1024] * B[N,1024]^T (+bias1+bias2)
//   Grid TRANSPOSED: blockIdx.x = M tile (16), blockIdx.y = N tile.
//   Consecutive CTAs share a B tile -> L2 reuse of the big weight matrix.
// ---------------------------------------------------------------------------
#define OPD_B   8192
#define STAGE_B (4 * OPD_B)
#define GEMM_SMEM_BYTES (2 * STAGE_B)
#define NSTAGE  (DIM / 32)

__global__ __launch_bounds__(256, 2) void gemm3_mma(
    int mode, const float* __restrict__ bias1, const float* __restrict__ bias2,
    float* __restrict__ outC) {
    const __nv_bfloat16* __restrict__ Ahi = g_Ahi;
    const __nv_bfloat16* __restrict__ Alo = g_Alo;
    const __nv_bfloat16* __restrict__ Bhi = mode ? g_Wohi : g_Wxhi;
    const __nv_bfloat16* __restrict__ Blo = mode ? g_Wolo : g_Wxlo;
    float* __restrict__ C = mode ? outC : g_Gx0;
    const int N = mode ? VOCAB : G4;

    extern __shared__ __align__(128) char smem[];
    const uint32_t sbase = smem_to_u32(smem);
    const int tid  = threadIdx.x;
    const int lane = tid & 31;
    const int warp = tid >> 5;
    const int wm   = warp & 3;
    const int wn   = warp >> 2;
    const int mTile = blockIdx.x * 128;     // M fastest -> B-tile reuse
    const int nTile = blockIdx.y * 128;

    const int gRow  = tid >> 1;
    const int cBase = (tid & 1) * 2;
    uint32_t sOff[2];
#pragma unroll
    for (int j = 0; j < 2; ++j) {
        const int c = cBase + j;
        sOff[j] = gRow * 64 + ((c ^ (gRow & 3)) << 4);
    }
    const __nv_bfloat16* pAh = Ahi + (size_t)(mTile + gRow) * DIM;
    const __nv_bfloat16* pAl = Alo + (size_t)(mTile + gRow) * DIM;
    const __nv_bfloat16* pBh = Bhi + (size_t)(nTile + gRow) * DIM;
    const __nv_bfloat16* pBl = Blo + (size_t)(nTile + gRow) * DIM;

#define PREFETCH(s)                                                            \
    do {                                                                       \
        const uint32_t db = sbase + ((s) & 1) * STAGE_B;                       \
        const int k0 = (s) * 32;                                               \
        _Pragma("unroll")                                                      \
        for (int j = 0; j < 2; ++j) {                                          \
            const int kh = k0 + (cBase + j) * 8;                               \
            cpa16(db + 0 * OPD_B + sOff[j], pAh + kh);                         \
            cpa16(db + 1 * OPD_B + sOff[j], pAl + kh);                         \
            cpa16(db + 2 * OPD_B + sOff[j], pBh + kh);                         \
            cpa16(db + 3 * OPD_B + sOff[j], pBl + kh);                         \
        }                                                                      \
        asm volatile("cp.async.commit_group;");                                \
    } while (0)

    float acc[2][8][4];
#pragma unroll
    for (int i = 0; i < 2; ++i)
#pragma unroll
        for (int j = 0; j < 8; ++j)
#pragma unroll
            for (int k = 0; k < 4; ++k) acc[i][j][k] = 0.f;

    PREFETCH(0);

    const int aRowB = wm * 32 + (lane & 7) + ((lane >> 3) & 1) * 8;
    const int bRowB = wn * 64 + (lane & 7) + ((lane >> 4) & 1) * 8;
    const int aCsel = (lane >> 4) & 1;
    const int bCsel = (lane >> 3) & 1;

    for (int s = 0; s < NSTAGE; ++s) {
        if (s + 1 < NSTAGE) {
            PREFETCH(s + 1);
            asm volatile("cp.async.wait_group 1;");
        } else {
            asm volatile("cp.async.wait_group 0;");
        }
        __syncthreads();

        const uint32_t sa = sbase + (s & 1) * STAGE_B;
#pragma unroll
        for (int ks = 0; ks < 2; ++ks) {
            uint32_t aHi[2][4], aLo[2][4], bHi[8][2], bLo[8][2];
            const int cA = ks * 2 + aCsel;
            const int cB = ks * 2 + bCsel;
#pragma unroll
            for (int mt = 0; mt < 2; ++mt) {
                const int r_ = aRowB + mt * 16;
                const uint32_t off = r_ * 64 + ((cA ^ (r_ & 3)) << 4);
                ldsm4(aHi[mt], sa + off);
                ldsm4(aLo[mt], sa + OPD_B + off);
            }
#pragma unroll
            for (int p = 0; p < 4; ++p) {
                const int r_ = bRowB + p * 16;
                const uint32_t off = r_ * 64 + ((cB ^ (r_ & 3)) << 4);
                ldsm4(&bHi[2 * p][0], sa + 2 * OPD_B + off);
                ldsm4(&bLo[2 * p][0], sa + 3 * OPD_B + off);
            }
#pragma unroll
            for (int mt = 0; mt < 2; ++mt)
#pragma unroll
                for (int nt = 0; nt < 8; ++nt) {
                    mma16816(acc[mt][nt], aHi[mt], bHi[nt]);
                    mma16816(acc[mt][nt], aHi[mt], bLo[nt]);
                    mma16816(acc[mt][nt], aLo[mt], bHi[nt]);
                }
        }
        __syncthreads();
    }

    const int mBaseW = mTile + wm * 32 + (lane >> 2);
    const int nBaseW = nTile + wn * 64 + (lane & 3) * 2;
#pragma unroll
    for (int mt = 0; mt < 2; ++mt)
#pragma unroll
        for (int nt = 0; nt < 8; ++nt) {
            const int n = nBaseW + nt * 8;
            float b0 = 0.f, b1 = 0.f;
            if (mode == 0) {
                b0 = bias1[n] + bias2[n];
                b1 = bias1[n + 1] + bias2[n + 1];
            }
            const int m0 = mBaseW + mt * 16;
            float2 v0 = make_float2(acc[mt][nt][0] + b0, acc[mt][nt][1] + b1);
            float2 v1 = make_float2(acc[mt][nt][2] + b0, acc[mt][nt][3] + b1);
            *(float2*)(C + (size_t)m0 * N + n)       = v0;
            *(float2*)(C + (size_t)(m0 + 8) * N + n) = v1;
        }
#undef PREFETCH
}

// ---------------------------------------------------------------------------
// Persistent LSTM recurrence. NEW: layer-0 weight slice (32 rows x 1024)
// cached in padded smem once; phase 0 runs entirely from smem.
// ---------------------------------------------------------------------------
#define GSYNC()                                                                  \
    do {                                                                         \
        __threadfence();                                                         \
        __syncthreads();                                                         \
        if (tid == 0) {                                                          \
            ++nbar;                                                              \
            unsigned t_ = atomicAdd(&g_bar_count, 1u) + 1u;                      \
            if (t_ % NBLK == 0u) {                                               \
                atomicAdd(&g_bar_gen, 1u);                                       \
            } else {                                                             \
                while ((int)(*((volatile unsigned*)&g_bar_gen) - s_base - nbar)  \
                       < 0) { }                                                  \
            }                                                                    \
            __threadfence();                                                     \
        }                                                                        \
        __syncthreads();                                                         \
    } while (0)

#define LSTM_SMEM_FLOATS (16 * HP + 1024 + 32 * WP)
#define LSTM_SMEM_BYTES  (LSTM_SMEM_FLOATS * 4)

__global__ __launch_bounds__(1024, 1) void lstm_kernel(
    const float* __restrict__ Wx, const float* __restrict__ bx,
    const float* __restrict__ Wh, const float* __restrict__ bh,
    float* __restrict__ d_out) {
    extern __shared__ float smemf[];
    float* hA    = smemf;                       // 8 x HP
    float* hB    = smemf + 8 * HP;              // 8 x HP
    float* gpart = smemf + 16 * HP;             // 1024
    float* w0    = smemf + 16 * HP + 1024;      // 32 x WP  (layer-0 Wh slice)

    const int tid  = threadIdx.x;
    const int w    = tid >> 5, lane = tid & 31;
    const int dl   = w >> 2,   kq   = w & 3;
    const int d    = (blockIdx.x << 3) + dl;
    const int gg   = lane >> 3, b = lane & 7;

    __shared__ unsigned s_base;
    if (tid == 0) s_base = *((volatile unsigned*)&g_bar_gen);

    {
        const int i = blockIdx.x * 1024 + tid;
        if (i < BATCH * DIM) { g_h0[i] = 0.f; g_h1[i] = 0.f; }
    }

    // cache layer-0 Wh slice: ru = gate*8 + unit_local, 256 float4 per row
    for (int f = tid; f < 32 * 256; f += 1024) {
        const int ru = f >> 8;               // 0..31
        const int kf = f & 255;
        const int grow = (ru >> 3) * 1024 + (blockIdx.x << 3) + (ru & 7);
        *(float4*)&w0[ru * WP + kf * 4] =
            *(const float4*)&Wh[(size_t)grow * DIM + kf * 4];
    }

    unsigned nbar = 0;
    GSYNC();

    const bool is_cell = (kq == 0) && (lane < 8);
    float c0r = 0.f, c1r = 0.f, h0l = 0.f, h1l = 0.f;
    float bi = 0.f, bf = 0.f, bo = 0.f, bg = 0.f;
    if (is_cell) {
        bi = bx[G4 + d]        + bh[G4 + d];
        bf = bx[G4 + 1024 + d] + bh[G4 + 1024 + d];
        bo = bx[G4 + 2048 + d] + bh[G4 + 2048 + d];
        bg = bx[G4 + 3072 + d] + bh[G4 + 3072 + d];
    }

    const int   r    = (gg << 10) + d;
    const float* w0r = w0 + (gg * 8 + dl) * WP + (kq << 8);
    const float* Wh1r = Wh + (size_t)G4 * DIM + (size_t)r * DIM + (kq << 8);
    const float* Wx1r = Wx + (size_t)G4 * DIM + (size_t)r * DIM + (kq << 8);
    const int gidx = ((kq << 3) + dl) * 32 + lane;

    for (int t = 0; t < SEQ; ++t) {
        // ---------- layer 0: gates = Gx0[b,t] + h0_prev @ Wh0^T (smem W) ----
        for (int i = tid; i < BATCH * DIM; i += 1024)
            hA[(i >> 10) * HP + (i & 1023)] = __ldcg(&g_h0[i]);
        __syncthreads();
        {
            float acc = 0.f;
            const float* hrow = hA + b * HP + (kq << 8);
#pragma unroll 8
            for (int kk = 0; kk < 256; kk += 4) {
                const float4 wv = *(const float4*)(w0r + kk);
                const float4 hv = *(const float4*)(hrow + kk);
                acc = fmaf(wv.x, hv.x, acc);
                acc = fmaf(wv.y, hv.y, acc);
                acc = fmaf(wv.z, hv.z, acc);
                acc = fmaf(wv.w, hv.w, acc);
            }
            gpart[gidx] = acc;
        }
        __syncthreads();
        if (is_cell) {
            float gate[4];
#pragma unroll
            for (int q = 0; q < 4; ++q) {
                float v = gpart[(0 * 8 + dl) * 32 + (q << 3) + lane]
                        + gpart[(1 * 8 + dl) * 32 + (q << 3) + lane]
                        + gpart[(2 * 8 + dl) * 32 + (q << 3) + lane]
                        + gpart[(3 * 8 + dl) * 32 + (q << 3) + lane];
                gate[q] = v + g_Gx0[(size_t)((lane << 8) + t) * G4 + (q << 10) + d];
            }
            const float ct = sigf(gate[1]) * c0r + sigf(gate[0]) * tanhf(gate[3]);
            const float ht = sigf(gate[2]) * tanhf(ct);
            c0r = ct; h0l = ht;
            g_h0[(lane << 10) + d] = ht;
        }
        GSYNC();

        // ---------- layer 1: gates = h0_t @ Wx1^T + h1_prev @ Wh1^T + b ----
        for (int i = tid; i < BATCH * DIM; i += 1024) {
            hA[(i >> 10) * HP + (i & 1023)] = __ldcg(&g_h0[i]);
            hB[(i >> 10) * HP + (i & 1023)] = __ldcg(&g_h1[i]);
        }
        __syncthreads();
        {
            float acc = 0.f;
            const float* h0row = hA + b * HP + (kq << 8);
            const float* h1row = hB + b * HP + (kq << 8);
#pragma unroll 4
            for (int kk = 0; kk < 256; kk += 4) {
                const float4 xv = *(const float4*)(Wx1r + kk);
                const float4 av = *(const float4*)(h0row + kk);
                const float4 wv = *(const float4*)(Wh1r + kk);
                const float4 bv = *(const float4*)(h1row + kk);
                acc = fmaf(xv.x, av.x, acc);
                acc = fmaf(xv.y, av.y, acc);
                acc = fmaf(xv.z, av.z, acc);
                acc = fmaf(xv.w, av.w, acc);
                acc = fmaf(wv.x, bv.x, acc);
                acc = fmaf(wv.y, bv.y, acc);
                acc = fmaf(wv.z, bv.z, acc);
                acc = fmaf(wv.w, bv.w, acc);
            }
            gpart[gidx] = acc;
        }
        __syncthreads();
        if (is_cell) {
            float gate[4];
#pragma unroll
            for (int q = 0; q < 4; ++q) {
                gate[q] = gpart[(0 * 8 + dl) * 32 + (q << 3) + lane]
                        + gpart[(1 * 8 + dl) * 32 + (q << 3) + lane]
                        + gpart[(2 * 8 + dl) * 32 + (q << 3) + lane]
                        + gpart[(3 * 8 + dl) * 32 + (q << 3) + lane];
            }
            gate[0] += bi; gate[1] += bf; gate[2] += bo; gate[3] += bg;
            const float ct = sigf(gate[1]) * c1r + sigf(gate[0]) * tanhf(gate[3]);
            const float ht = sigf(gate[2]) * tanhf(ct);
            c1r = ct; h1l = ht;
            g_h1[(lane << 10) + d] = ht;
            g_lstm_out[(size_t)((lane << 8) + t) * DIM + d] = ht;
        }
        GSYNC();
    }

    if (is_cell) {
        const size_t LOGN = (size_t)ROWS * VOCAB;
        d_out[LOGN + (lane << 10) + d]                   = h0l;
        d_out[LOGN + BATCH * DIM + (lane << 10) + d]     = h1l;
        d_out[LOGN + 2 * BATCH * DIM + (lane << 10) + d] = c0r;
        d_out[LOGN + 3 * BATCH * DIM + (lane << 10) + d] = c1r;
    }
}

// ---------------------------------------------------------------------------
// RMSNorm (fp32)
// ---------------------------------------------------------------------------
__global__ __launch_bounds__(256) void rmsnorm_kernel(const float* __restrict__ w) {
    const int row = blockIdx.x, tid = threadIdx.x;
    const float4 v = *(((const float4*)(g_lstm_out + (size_t)row * DIM)) + tid);
    float ss = v.x * v.x + v.y * v.y + v.z * v.z + v.w * v.w;
#pragma unroll
    for (int o = 16; o; o >>= 1) ss += __shfl_xor_sync(0xffffffffu, ss, o);
    __shared__ float sred[8];
    __shared__ float sinv;
    if ((tid & 31) == 0) sred[tid >> 5] = ss;
    __syncthreads();
    if (tid == 0) {
        float tot = 0.f;
#pragma unroll
        for (int i = 0; i < 8; i++) tot += sred[i];
        sinv = rsqrtf(tot * (1.f / 1024.f) + 1e-5f);
    }
    __syncthreads();
    const float inv = sinv;
    const float4 wv = ((const float4*)w)[tid];
    float4 o4;
    o4.x = v.x * inv * wv.x;
    o4.y = v.y * inv * wv.y;
    o4.z = v.z * inv * wv.z;
    o4.w = v.w * inv * wv.w;
    *(((float4*)(g_normed + (size_t)row * DIM)) + tid) = o4;
}

// ---------------------------------------------------------------------------
// Launch — lstm_kernel deliberately placed at launch index 3 (ncu slot)
// ---------------------------------------------------------------------------
extern "C" void kernel_launch(void* const* d_in, const int* in_sizes, int n_in,
                              void* d_out, int out_size) {
    (void)in_sizes; (void)n_in; (void)out_size;
    const int*   ids  = (const int*)d_in[0];
    const float* emb  = (const float*)d_in[1];
    const float* Wx   = (const float*)d_in[2];
    const float* bx   = (const float*)d_in[3];
    const float* Wh   = (const float*)d_in[4];
    const float* bh   = (const float*)d_in[5];
    const float* nw   = (const float*)d_in[6];
    const float* Wout = (const float*)d_in[7];
    float* out = (float*)d_out;

    cudaFuncSetAttribute(lstm_kernel, cudaFuncAttributeMaxDynamicSharedMemorySize,
                         LSTM_SMEM_BYTES);
    cudaFuncSetAttribute(gemm3_mma, cudaFuncAttributeMaxDynamicSharedMemorySize,
                         GEMM_SMEM_BYTES);

    embed_split_kernel<<<ROWS, 256>>>(ids, emb);                       // 0
    convertW_kernel<<<4096, 256>>>(Wx, Wout);                          // 1
    gemm3_mma<<<dim3(ROWS / 128, G4 / 128), 256, GEMM_SMEM_BYTES>>>(   // 2
        0, bx, bh, out);
    lstm_kernel<<<NBLK, 1024, LSTM_SMEM_BYTES>>>(Wx, bx, Wh, bh, out); // 3 (ncu)
    rmsnorm_kernel<<<ROWS, 256>>>(nw);                                 // 4
    conv_normed_kernel<<<2048, 256>>>();                               // 5
    gemm3_mma<<<dim3(ROWS / 128, VOCAB / 128), 256, GEMM_SMEM_BYTES>>>(// 6
        1, nullptr, nullptr, out);
}

// round 14
// speedup vs baseline: 1.5464x; 1.2557x over previous
#include <cuda_runtime.h>
#include <cuda_bf16.h>
#include <math.h>
#include <cstdint>

// ---------------------------------------------------------------------------
// Problem constants
// ---------------------------------------------------------------------------
#define BATCH   8
#define SEQ     256
#define DIM     1024
#define G4      4096        // 4*DIM
#define VOCAB   32000
#define ROWS    2048        // BATCH*SEQ
#define NBLK    128         // persistent LSTM grid
#define HP      1028        // padded row stride for h in smem
#define WP      1028        // padded row stride for cached weights

// ---------------------------------------------------------------------------
// Device-global scratch (device-side references only — never host args)
// ---------------------------------------------------------------------------
__device__ __align__(256) float g_Gx0[ROWS * G4];      // layer-0 x-path gates
__device__ __align__(256) float g_Gx1[ROWS * G4];      // layer-1 x-path gates
__device__ __align__(256) float g_h0seq[ROWS * DIM];   // all h0_t
__device__ __align__(256) float g_lstm_out[ROWS * DIM];
__device__ __align__(256) float g_normed[ROWS * DIM];
__device__ __align__(256) float g_h0[BATCH * DIM];     // live hidden state
__device__ int g_arrive[NBLK];
__device__ int g_release = 0;

// split-bf16 operands
__device__ __align__(256) __nv_bfloat16 g_Ahi[ROWS * DIM],   g_Alo[ROWS * DIM];
__device__ __align__(256) __nv_bfloat16 g_Wxhi[2 * G4 * DIM], g_Wxlo[2 * G4 * DIM];
__device__ __align__(256) __nv_bfloat16 g_Wohi[VOCAB * DIM],  g_Wolo[VOCAB * DIM];

__device__ __forceinline__ float sigf(float x) { return 1.f / (1.f + expf(-x)); }

__device__ __forceinline__ uint32_t smem_to_u32(const void* p) {
    uint32_t a;
    asm("{ .reg .u64 t; cvta.to.shared.u64 t, %1; cvt.u32.u64 %0, t; }"
        : "=r"(a) : "l"(p));
    return a;
}
__device__ __forceinline__ void cpa16(uint32_t dst, const void* src) {
    asm volatile("cp.async.cg.shared.global [%0], [%1], 16;"
                 :: "r"(dst), "l"(src));
}
__device__ __forceinline__ void ldsm4(uint32_t* r, uint32_t addr) {
    asm volatile("ldmatrix.sync.aligned.m8n8.x4.shared.b16 {%0,%1,%2,%3}, [%4];"
                 : "=r"(r[0]), "=r"(r[1]), "=r"(r[2]), "=r"(r[3]) : "r"(addr));
}
__device__ __forceinline__ void mma16816(float* d, const uint32_t* a,
                                         const uint32_t* b) {
    asm volatile(
        "mma.sync.aligned.m16n8k16.row.col.f32.bf16.bf16.f32 "
        "{%0,%1,%2,%3},{%4,%5,%6,%7},{%8,%9},{%0,%1,%2,%3};"
        : "+f"(d[0]), "+f"(d[1]), "+f"(d[2]), "+f"(d[3])
        : "r"(a[0]), "r"(a[1]), "r"(a[2]), "r"(a[3]), "r"(b[0]), "r"(b[1]));
}

// ---------------------------------------------------------------------------
// Embedding gather fused with hi/lo bf16 split
// ---------------------------------------------------------------------------
__global__ __launch_bounds__(256) void embed_split_kernel(
    const int* __restrict__ ids, const float* __restrict__ emb) {
    const int row = blockIdx.x;
    const int id  = ids[row];
    const float4 v = ((const float4*)(emb + (size_t)id * DIM))[threadIdx.x];
    const size_t base = (size_t)row * DIM + threadIdx.x * 4;
    __nv_bfloat162* hi2 = (__nv_bfloat162*)(g_Ahi + base);
    __nv_bfloat162* lo2 = (__nv_bfloat162*)(g_Alo + base);
    __nv_bfloat162 h0 = __floats2bfloat162_rn(v.x, v.y);
    __nv_bfloat162 h1 = __floats2bfloat162_rn(v.z, v.w);
    hi2[0] = h0;
    hi2[1] = h1;
    lo2[0] = __floats2bfloat162_rn(v.x - __bfloat162float(__low2bfloat16(h0)),
                                   v.y - __bfloat162float(__high2bfloat16(h0)));
    lo2[1] = __floats2bfloat162_rn(v.z - __bfloat162float(__low2bfloat16(h1)),
                                   v.w - __bfloat162float(__high2bfloat16(h1)));
}

// ---------------------------------------------------------------------------
// Weight matrices (Wx both layers + Wout) -> hi/lo bf16 in one launch
// ---------------------------------------------------------------------------
#define NWX (2 * G4 * DIM)
#define NWO (VOCAB * DIM)
__global__ __launch_bounds__(256) void convertW_kernel(
    const float* __restrict__ Wx, const float* __restrict__ Wout) {
    int i = blockIdx.x * blockDim.x + threadIdx.x;
    const int stride = gridDim.x * blockDim.x;
    for (; i < NWX + NWO; i += stride) {
        float x;
        __nv_bfloat16 *hip, *lop;
        if (i < NWX) {
            x = Wx[i]; hip = g_Wxhi + i; lop = g_Wxlo + i;
        } else {
            const int j = i - NWX;
            x = Wout[j]; hip = g_Wohi + j; lop = g_Wolo + j;
        }
        const __nv_bfloat16 h = __float2bfloat16_rn(x);
        *hip = h;
        *lop = __float2bfloat16_rn(x - __bfloat162float(h));
    }
}

// ---------------------------------------------------------------------------
// g_h0seq (mode 0) or g_normed (mode 1) -> g_Ahi/g_Alo
// ---------------------------------------------------------------------------
__global__ __launch_bounds__(256) void conv_AhiAlo_kernel(int mode) {
    const float* __restrict__ src = mode ? g_normed : g_h0seq;
    int i = blockIdx.x * blockDim.x + threadIdx.x;
    const int stride = gridDim.x * blockDim.x;
    for (; i < ROWS * DIM; i += stride) {
        const float x = src[i];
        const __nv_bfloat16 h = __float2bfloat16_rn(x);
        g_Ahi[i] = h;
        g_Alo[i] = __float2bfloat16_rn(x - __bfloat162float(h));
    }
}

// ---------------------------------------------------------------------------
// Split-bf16 HMMA GEMM: C[M,N] = A[M,1024] * B[N,1024]^T (+bias1+bias2)
//   mode 0: B=Wx layer0 -> g_Gx0 (N=G4, bias)
//   mode 2: B=Wx layer1 -> g_Gx1 (N=G4, bias)
//   mode 1: B=Wout      -> outC  (N=VOCAB, no bias)
// ---------------------------------------------------------------------------
#define OPD_B   8192
#define STAGE_B (4 * OPD_B)
#define GEMM_SMEM_BYTES (2 * STAGE_B)
#define NSTAGE  (DIM / 32)

__global__ __launch_bounds__(256, 2) void gemm3_mma(
    int mode, const float* __restrict__ bias1, const float* __restrict__ bias2,
    float* __restrict__ outC) {
    const __nv_bfloat16* __restrict__ Ahi = g_Ahi;
    const __nv_bfloat16* __restrict__ Alo = g_Alo;
    const __nv_bfloat16* __restrict__ Bhi =
        (mode == 1) ? g_Wohi : g_Wxhi + (mode == 2 ? (size_t)G4 * DIM : 0);
    const __nv_bfloat16* __restrict__ Blo =
        (mode == 1) ? g_Wolo : g_Wxlo + (mode == 2 ? (size_t)G4 * DIM : 0);
    float* __restrict__ C = (mode == 1) ? outC : (mode == 2 ? g_Gx1 : g_Gx0);
    const int N = (mode == 1) ? VOCAB : G4;

    extern __shared__ __align__(128) char smem[];
    const uint32_t sbase = smem_to_u32(smem);
    const int tid  = threadIdx.x;
    const int lane = tid & 31;
    const int warp = tid >> 5;
    const int wm   = warp & 3;
    const int wn   = warp >> 2;
    const int mTile = blockIdx.x * 128;     // M fastest -> B-tile L2 reuse
    const int nTile = blockIdx.y * 128;

    const int gRow  = tid >> 1;
    const int cBase = (tid & 1) * 2;
    uint32_t sOff[2];
#pragma unroll
    for (int j = 0; j < 2; ++j) {
        const int c = cBase + j;
        sOff[j] = gRow * 64 + ((c ^ (gRow & 3)) << 4);
    }
    const __nv_bfloat16* pAh = Ahi + (size_t)(mTile + gRow) * DIM;
    const __nv_bfloat16* pAl = Alo + (size_t)(mTile + gRow) * DIM;
    const __nv_bfloat16* pBh = Bhi + (size_t)(nTile + gRow) * DIM;
    const __nv_bfloat16* pBl = Blo + (size_t)(nTile + gRow) * DIM;

#define PREFETCH(s)                                                            \
    do {                                                                       \
        const uint32_t db = sbase + ((s) & 1) * STAGE_B;                       \
        const int k0 = (s) * 32;                                               \
        _Pragma("unroll")                                                      \
        for (int j = 0; j < 2; ++j) {                                          \
            const int kh = k0 + (cBase + j) * 8;                               \
            cpa16(db + 0 * OPD_B + sOff[j], pAh + kh);                         \
            cpa16(db + 1 * OPD_B + sOff[j], pAl + kh);                         \
            cpa16(db + 2 * OPD_B + sOff[j], pBh + kh);                         \
            cpa16(db + 3 * OPD_B + sOff[j], pBl + kh);                         \
        }                                                                      \
        asm volatile("cp.async.commit_group;");                                \
    } while (0)

    float acc[2][8][4];
#pragma unroll
    for (int i = 0; i < 2; ++i)
#pragma unroll
        for (int j = 0; j < 8; ++j)
#pragma unroll
            for (int k = 0; k < 4; ++k) acc[i][j][k] = 0.f;

    PREFETCH(0);

    const int aRowB = wm * 32 + (lane & 7) + ((lane >> 3) & 1) * 8;
    const int bRowB = wn * 64 + (lane & 7) + ((lane >> 4) & 1) * 8;
    const int aCsel = (lane >> 4) & 1;
    const int bCsel = (lane >> 3) & 1;

    for (int s = 0; s < NSTAGE; ++s) {
        if (s + 1 < NSTAGE) {
            PREFETCH(s + 1);
            asm volatile("cp.async.wait_group 1;");
        } else {
            asm volatile("cp.async.wait_group 0;");
        }
        __syncthreads();

        const uint32_t sa = sbase + (s & 1) * STAGE_B;
#pragma unroll
        for (int ks = 0; ks < 2; ++ks) {
            uint32_t aHi[2][4], aLo[2][4], bHi[8][2], bLo[8][2];
            const int cA = ks * 2 + aCsel;
            const int cB = ks * 2 + bCsel;
#pragma unroll
            for (int mt = 0; mt < 2; ++mt) {
                const int r_ = aRowB + mt * 16;
                const uint32_t off = r_ * 64 + ((cA ^ (r_ & 3)) << 4);
                ldsm4(aHi[mt], sa + off);
                ldsm4(aLo[mt], sa + OPD_B + off);
            }
#pragma unroll
            for (int p = 0; p < 4; ++p) {
                const int r_ = bRowB + p * 16;
                const uint32_t off = r_ * 64 + ((cB ^ (r_ & 3)) << 4);
                ldsm4(&bHi[2 * p][0], sa + 2 * OPD_B + off);
                ldsm4(&bLo[2 * p][0], sa + 3 * OPD_B + off);
            }
#pragma unroll
            for (int mt = 0; mt < 2; ++mt)
#pragma unroll
                for (int nt = 0; nt < 8; ++nt) {
                    mma16816(acc[mt][nt], aHi[mt], bHi[nt]);
                    mma16816(acc[mt][nt], aHi[mt], bLo[nt]);
                    mma16816(acc[mt][nt], aLo[mt], bHi[nt]);
                }
        }
        __syncthreads();
    }

    const int mBaseW = mTile + wm * 32 + (lane >> 2);
    const int nBaseW = nTile + wn * 64 + (lane & 3) * 2;
#pragma unroll
    for (int mt = 0; mt < 2; ++mt)
#pragma unroll
        for (int nt = 0; nt < 8; ++nt) {
            const int n = nBaseW + nt * 8;
            float b0 = 0.f, b1 = 0.f;
            if (mode != 1) {
                b0 = bias1[n] + bias2[n];
                b1 = bias1[n + 1] + bias2[n + 1];
            }
            const int m0 = mBaseW + mt * 16;
            float2 v0 = make_float2(acc[mt][nt][0] + b0, acc[mt][nt][1] + b1);
            float2 v1 = make_float2(acc[mt][nt][2] + b0, acc[mt][nt][3] + b1);
            *(float2*)(C + (size_t)m0 * N + n)       = v0;
            *(float2*)(C + (size_t)(m0 + 8) * N + n) = v1;
        }
#undef PREFETCH
}

// ---------------------------------------------------------------------------
// Flag-tree grid barrier: parallel arrivals, CTA0 aggregates, release word.
// Epochs are monotonic across launches/replays (g_release read at entry).
// ---------------------------------------------------------------------------
#define GSYNC()                                                                  \
    do {                                                                         \
        __syncthreads();                                                         \
        ++nbar;                                                                  \
        const int target_ = s_base + nbar;                                       \
        if (tid == 0) {                                                          \
            __threadfence();                                                     \
            *((volatile int*)&g_arrive[blockIdx.x]) = target_;                   \
        }                                                                        \
        if (blockIdx.x == 0) {                                                   \
            if (tid < NBLK) {                                                    \
                while (*((volatile int*)&g_arrive[tid]) - target_ < 0) {}        \
            }                                                                    \
            __syncthreads();                                                     \
            if (tid == 0) {                                                      \
                __threadfence();                                                 \
                *((volatile int*)&g_release) = target_;                          \
            }                                                                    \
        } else if (tid == 0) {                                                   \
            while (*((volatile int*)&g_release) - target_ < 0) {}                \
            __threadfence();                                                     \
        }                                                                        \
        __syncthreads();                                                         \
    } while (0)

// ---------------------------------------------------------------------------
// One-layer recurrence pass. Wh slice (32 rows x 1024 = 128 KB) lives in smem
// for the whole pass; gate x-path comes precomputed from g_Gx{0,1}.
//   gates = Gx[b,t] + h_prev @ Wh_l^T ; cell update; h written to g_h0 + hseq.
// ---------------------------------------------------------------------------
#define LSTMP_SMEM_FLOATS (32 * WP + 8 * HP + 1024)
#define LSTMP_SMEM_BYTES  (LSTMP_SMEM_FLOATS * 4)

__global__ __launch_bounds__(1024, 1) void lstm_pass_kernel(
    const float* __restrict__ Wh, int layer, float* __restrict__ d_out) {
    extern __shared__ float smemf[];
    float* w0    = smemf;                       // 32 x WP
    float* hA    = smemf + 32 * WP;             // 8 x HP
    float* gpart = smemf + 32 * WP + 8 * HP;    // 1024

    const int tid  = threadIdx.x;
    const int w    = tid >> 5, lane = tid & 31;
    const int dl   = w >> 2,   kq   = w & 3;
    const int d    = (blockIdx.x << 3) + dl;
    const int gg   = lane >> 3, b = lane & 7;

    const float* __restrict__ gx = layer ? g_Gx1 : g_Gx0;
    float* __restrict__ hseq     = layer ? g_lstm_out : g_h0seq;

    __shared__ int s_base;
    if (tid == 0) s_base = *((volatile int*)&g_release);

    // zero live hidden state (blocks 0..7)
    if (blockIdx.x < 8) g_h0[blockIdx.x * 1024 + tid] = 0.f;

    // cache this layer's Wh slice: ru = gate*8 + unit_local
    for (int f = tid; f < 32 * 256; f += 1024) {
        const int ru = f >> 8;
        const int kf = f & 255;
        const int grow = layer * G4 + (ru >> 3) * 1024 + (blockIdx.x << 3) + (ru & 7);
        *(float4*)&w0[ru * WP + kf * 4] =
            *(const float4*)&Wh[(size_t)grow * DIM + kf * 4];
    }

    int nbar = 0;
    GSYNC();   // h zeroed + s_base consistent everywhere

    const bool is_cell = (kq == 0) && (lane < 8);
    float c_l = 0.f, h_l = 0.f;

    const float* wr = w0 + (gg * 8 + dl) * WP + (kq << 8);
    const int gidx  = ((kq << 3) + dl) * 32 + lane;

    for (int t = 0; t < SEQ; ++t) {
        // stage h_prev into smem
        for (int i = tid; i < BATCH * DIM; i += 1024)
            hA[(i >> 10) * HP + (i & 1023)] = __ldcg(&g_h0[i]);
        __syncthreads();

        // quarter dot product from smem
        {
            float acc = 0.f;
            const float* hr = hA + b * HP + (kq << 8);
#pragma unroll 8
            for (int kk = 0; kk < 256; kk += 4) {
                const float4 wv = *(const float4*)(wr + kk);
                const float4 hv = *(const float4*)(hr + kk);
                acc = fmaf(wv.x, hv.x, acc);
                acc = fmaf(wv.y, hv.y, acc);
                acc = fmaf(wv.z, hv.z, acc);
                acc = fmaf(wv.w, hv.w, acc);
            }
            gpart[gidx] = acc;
        }
        __syncthreads();

        if (is_cell) {
            float gate[4];
#pragma unroll
            for (int q = 0; q < 4; ++q) {
                float v = gpart[(0 * 8 + dl) * 32 + (q << 3) + lane]
                        + gpart[(1 * 8 + dl) * 32 + (q << 3) + lane]
                        + gpart[(2 * 8 + dl) * 32 + (q << 3) + lane]
                        + gpart[(3 * 8 + dl) * 32 + (q << 3) + lane];
                gate[q] = v + __ldcg(&gx[(size_t)((b << 8) + t) * G4 + (q << 10) + d]);
            }
            const float ct = sigf(gate[1]) * c_l + sigf(gate[0]) * tanhf(gate[3]);
            const float ht = sigf(gate[2]) * tanhf(ct);
            c_l = ct; h_l = ht;
            g_h0[(b << 10) + d] = ht;
            hseq[(size_t)((b << 8) + t) * DIM + d] = ht;
        }
        GSYNC();
    }

    // finals: d_out = [logits | h_n(L,B,D) | c_n(L,B,D)]
    if (is_cell) {
        const size_t LOGN = (size_t)ROWS * VOCAB;
        d_out[LOGN + (size_t)layer * BATCH * DIM + (b << 10) + d]                    = h_l;
        d_out[LOGN + 2 * BATCH * DIM + (size_t)layer * BATCH * DIM + (b << 10) + d]  = c_l;
    }
}

// ---------------------------------------------------------------------------
// RMSNorm (fp32)
// ---------------------------------------------------------------------------
__global__ __launch_bounds__(256) void rmsnorm_kernel(const float* __restrict__ w) {
    const int row = blockIdx.x, tid = threadIdx.x;
    const float4 v = *(((const float4*)(g_lstm_out + (size_t)row * DIM)) + tid);
    float ss = v.x * v.x + v.y * v.y + v.z * v.z + v.w * v.w;
#pragma unroll
    for (int o = 16; o; o >>= 1) ss += __shfl_xor_sync(0xffffffffu, ss, o);
    __shared__ float sred[8];
    __shared__ float sinv;
    if ((tid & 31) == 0) sred[tid >> 5] = ss;
    __syncthreads();
    if (tid == 0) {
        float tot = 0.f;
#pragma unroll
        for (int i = 0; i < 8; i++) tot += sred[i];
        sinv = rsqrtf(tot * (1.f / 1024.f) + 1e-5f);
    }
    __syncthreads();
    const float inv = sinv;
    const float4 wv = ((const float4*)w)[tid];
    float4 o4;
    o4.x = v.x * inv * wv.x;
    o4.y = v.y * inv * wv.y;
    o4.z = v.z * inv * wv.z;
    o4.w = v.w * inv * wv.w;
    *(((float4*)(g_normed + (size_t)row * DIM)) + tid) = o4;
}

// ---------------------------------------------------------------------------
// Launch — pass A at index 3 (ncu slot)
// ---------------------------------------------------------------------------
extern "C" void kernel_launch(void* const* d_in, const int* in_sizes, int n_in,
                              void* d_out, int out_size) {
    (void)in_sizes; (void)n_in; (void)out_size;
    const int*   ids  = (const int*)d_in[0];
    const float* emb  = (const float*)d_in[1];
    const float* Wx   = (const float*)d_in[2];
    const float* bx   = (const float*)d_in[3];
    const float* Wh   = (const float*)d_in[4];
    const float* bh   = (const float*)d_in[5];
    const float* nw   = (const float*)d_in[6];
    const float* Wout = (const float*)d_in[7];
    float* out = (float*)d_out;

    cudaFuncSetAttribute(lstm_pass_kernel, cudaFuncAttributeMaxDynamicSharedMemorySize,
                         LSTMP_SMEM_BYTES);
    cudaFuncSetAttribute(gemm3_mma, cudaFuncAttributeMaxDynamicSharedMemorySize,
                         GEMM_SMEM_BYTES);

    embed_split_kernel<<<ROWS, 256>>>(ids, emb);                            // 0
    convertW_kernel<<<4096, 256>>>(Wx, Wout);                               // 1
    gemm3_mma<<<dim3(ROWS / 128, G4 / 128), 256, GEMM_SMEM_BYTES>>>(        // 2
        0, bx, bh, out);
    lstm_pass_kernel<<<NBLK, 1024, LSTMP_SMEM_BYTES>>>(Wh, 0, out);         // 3 (ncu)
    conv_AhiAlo_kernel<<<2048, 256>>>(0);                                   // 4
    gemm3_mma<<<dim3(ROWS / 128, G4 / 128), 256, GEMM_SMEM_BYTES>>>(        // 5
        2, bx + G4, bh + G4, out);
    lstm_pass_kernel<<<NBLK, 1024, LSTMP_SMEM_BYTES>>>(Wh, 1, out);         // 6
    rmsnorm_kernel<<<ROWS, 256>>>(nw);                                      // 7
    conv_AhiAlo_kernel<<<2048, 256>>>(1);                                   // 8
    gemm3_mma<<<dim3(ROWS / 128, VOCAB / 128), 256, GEMM_SMEM_BYTES>>>(     // 9
        1, nullptr, nullptr, out);
}

// round 15
// speedup vs baseline: 2.4407x; 1.5783x over previous
#include <cuda_runtime.h>
#include <cuda_bf16.h>
#include <math.h>
#include <cstdint>

// ---------------------------------------------------------------------------
// Problem constants
// ---------------------------------------------------------------------------
#define BATCH   8
#define SEQ     256
#define DIM     1024
#define G4      4096        // 4*DIM
#define VOCAB   32000
#define ROWS    2048        // BATCH*SEQ
#define NBLK    128         // persistent LSTM grid
#define HP      1028        // padded row stride (floats) -> conflict-free LDS.128
#define WP      1028

// ---------------------------------------------------------------------------
// Device-global scratch (device-side references only — never host args)
// ---------------------------------------------------------------------------
__device__ __align__(256) float g_Gx0[ROWS * G4];      // layer-0 x-path gates
__device__ __align__(256) float g_Gx1[ROWS * G4];      // layer-1 x-path gates
__device__ __align__(256) float g_h0seq[ROWS * DIM];   // all h0_t
__device__ __align__(256) float g_lstm_out[ROWS * DIM];
__device__ __align__(256) float g_normed[ROWS * DIM];
__device__ __align__(256) float g_h0[BATCH * DIM];     // live hidden state
__device__ int g_arrive[NBLK];
__device__ int g_release = 0;

// split-bf16 operands
__device__ __align__(256) __nv_bfloat16 g_Ahi[ROWS * DIM],   g_Alo[ROWS * DIM];
__device__ __align__(256) __nv_bfloat16 g_Wxhi[2 * G4 * DIM], g_Wxlo[2 * G4 * DIM];
__device__ __align__(256) __nv_bfloat16 g_Wohi[VOCAB * DIM],  g_Wolo[VOCAB * DIM];

__device__ __forceinline__ float sigf(float x) { return 1.f / (1.f + expf(-x)); }

__device__ __forceinline__ uint32_t smem_to_u32(const void* p) {
    uint32_t a;
    asm("{ .reg .u64 t; cvta.to.shared.u64 t, %1; cvt.u32.u64 %0, t; }"
        : "=r"(a) : "l"(p));
    return a;
}
__device__ __forceinline__ void cpa16(uint32_t dst, const void* src) {
    asm volatile("cp.async.cg.shared.global [%0], [%1], 16;"
                 :: "r"(dst), "l"(src));
}
__device__ __forceinline__ void ldsm4(uint32_t* r, uint32_t addr) {
    asm volatile("ldmatrix.sync.aligned.m8n8.x4.shared.b16 {%0,%1,%2,%3}, [%4];"
                 : "=r"(r[0]), "=r"(r[1]), "=r"(r[2]), "=r"(r[3]) : "r"(addr));
}
__device__ __forceinline__ void mma16816(float* d, const uint32_t* a,
                                         const uint32_t* b) {
    asm volatile(
        "mma.sync.aligned.m16n8k16.row.col.f32.bf16.bf16.f32 "
        "{%0,%1,%2,%3},{%4,%5,%6,%7},{%8,%9},{%0,%1,%2,%3};"
        : "+f"(d[0]), "+f"(d[1]), "+f"(d[2]), "+f"(d[3])
        : "r"(a[0]), "r"(a[1]), "r"(a[2]), "r"(a[3]), "r"(b[0]), "r"(b[1]));
}
// Blackwell packed fp32 FMA (PTX ISA 8.6, sm_100+ base — not arch-'a' gated)
__device__ __forceinline__ void ffma2(unsigned long long& d,
                                      unsigned long long a, unsigned long long b) {
    asm("fma.rn.f32x2 %0, %1, %2, %0;" : "+l"(d) : "l"(a), "l"(b));
}
__device__ __forceinline__ float f32x2_sum(unsigned long long v) {
    float lo, hi;
    asm("mov.b64 {%0,%1}, %2;" : "=f"(lo), "=f"(hi) : "l"(v));
    return lo + hi;
}

// ---------------------------------------------------------------------------
// Embedding gather fused with hi/lo bf16 split
// ---------------------------------------------------------------------------
__global__ __launch_bounds__(256) void embed_split_kernel(
    const int* __restrict__ ids, const float* __restrict__ emb) {
    const int row = blockIdx.x;
    const int id  = ids[row];
    const float4 v = ((const float4*)(emb + (size_t)id * DIM))[threadIdx.x];
    const size_t base = (size_t)row * DIM + threadIdx.x * 4;
    __nv_bfloat162* hi2 = (__nv_bfloat162*)(g_Ahi + base);
    __nv_bfloat162* lo2 = (__nv_bfloat162*)(g_Alo + base);
    __nv_bfloat162 h0 = __floats2bfloat162_rn(v.x, v.y);
    __nv_bfloat162 h1 = __floats2bfloat162_rn(v.z, v.w);
    hi2[0] = h0;
    hi2[1] = h1;
    lo2[0] = __floats2bfloat162_rn(v.x - __bfloat162float(__low2bfloat16(h0)),
                                   v.y - __bfloat162float(__high2bfloat16(h0)));
    lo2[1] = __floats2bfloat162_rn(v.z - __bfloat162float(__low2bfloat16(h1)),
                                   v.w - __bfloat162float(__high2bfloat16(h1)));
}

// ---------------------------------------------------------------------------
// Weight matrices (Wx both layers + Wout) -> hi/lo bf16 in one launch
// ---------------------------------------------------------------------------
#define NWX (2 * G4 * DIM)
#define NWO (VOCAB * DIM)
__global__ __launch_bounds__(256) void convertW_kernel(
    const float* __restrict__ Wx, const float* __restrict__ Wout) {
    int i = blockIdx.x * blockDim.x + threadIdx.x;
    const int stride = gridDim.x * blockDim.x;
    for (; i < NWX + NWO; i += stride) {
        float x;
        __nv_bfloat16 *hip, *lop;
        if (i < NWX) {
            x = Wx[i]; hip = g_Wxhi + i; lop = g_Wxlo + i;
        } else {
            const int j = i - NWX;
            x = Wout[j]; hip = g_Wohi + j; lop = g_Wolo + j;
        }
        const __nv_bfloat16 h = __float2bfloat16_rn(x);
        *hip = h;
        *lop = __float2bfloat16_rn(x - __bfloat162float(h));
    }
}

// ---------------------------------------------------------------------------
// g_h0seq (mode 0) or g_normed (mode 1) -> g_Ahi/g_Alo
// ---------------------------------------------------------------------------
__global__ __launch_bounds__(256) void conv_AhiAlo_kernel(int mode) {
    const float* __restrict__ src = mode ? g_normed : g_h0seq;
    int i = blockIdx.x * blockDim.x + threadIdx.x;
    const int stride = gridDim.x * blockDim.x;
    for (; i < ROWS * DIM; i += stride) {
        const float x = src[i];
        const __nv_bfloat16 h = __float2bfloat16_rn(x);
        g_Ahi[i] = h;
        g_Alo[i] = __float2bfloat16_rn(x - __bfloat162float(h));
    }
}

// ---------------------------------------------------------------------------
// Split-bf16 HMMA GEMM (unchanged)
// ---------------------------------------------------------------------------
#define OPD_B   8192
#define STAGE_B (4 * OPD_B)
#define GEMM_SMEM_BYTES (2 * STAGE_B)
#define NSTAGE  (DIM / 32)

__global__ __launch_bounds__(256, 2) void gemm3_mma(
    int mode, const float* __restrict__ bias1, const float* __restrict__ bias2,
    float* __restrict__ outC) {
    const __nv_bfloat16* __restrict__ Ahi = g_Ahi;
    const __nv_bfloat16* __restrict__ Alo = g_Alo;
    const __nv_bfloat16* __restrict__ Bhi =
        (mode == 1) ? g_Wohi : g_Wxhi + (mode == 2 ? (size_t)G4 * DIM : 0);
    const __nv_bfloat16* __restrict__ Blo =
        (mode == 1) ? g_Wolo : g_Wxlo + (mode == 2 ? (size_t)G4 * DIM : 0);
    float* __restrict__ C = (mode == 1) ? outC : (mode == 2 ? g_Gx1 : g_Gx0);
    const int N = (mode == 1) ? VOCAB : G4;

    extern __shared__ __align__(128) char smem[];
    const uint32_t sbase = smem_to_u32(smem);
    const int tid  = threadIdx.x;
    const int lane = tid & 31;
    const int warp = tid >> 5;
    const int wm   = warp & 3;
    const int wn   = warp >> 2;
    const int mTile = blockIdx.x * 128;
    const int nTile = blockIdx.y * 128;

    const int gRow  = tid >> 1;
    const int cBase = (tid & 1) * 2;
    uint32_t sOff[2];
#pragma unroll
    for (int j = 0; j < 2; ++j) {
        const int c = cBase + j;
        sOff[j] = gRow * 64 + ((c ^ (gRow & 3)) << 4);
    }
    const __nv_bfloat16* pAh = Ahi + (size_t)(mTile + gRow) * DIM;
    const __nv_bfloat16* pAl = Alo + (size_t)(mTile + gRow) * DIM;
    const __nv_bfloat16* pBh = Bhi + (size_t)(nTile + gRow) * DIM;
    const __nv_bfloat16* pBl = Blo + (size_t)(nTile + gRow) * DIM;

#define PREFETCH(s)                                                            \
    do {                                                                       \
        const uint32_t db = sbase + ((s) & 1) * STAGE_B;                       \
        const int k0 = (s) * 32;                                               \
        _Pragma("unroll")                                                      \
        for (int j = 0; j < 2; ++j) {                                          \
            const int kh = k0 + (cBase + j) * 8;                               \
            cpa16(db + 0 * OPD_B + sOff[j], pAh + kh);                         \
            cpa16(db + 1 * OPD_B + sOff[j], pAl + kh);                         \
            cpa16(db + 2 * OPD_B + sOff[j], pBh + kh);                         \
            cpa16(db + 3 * OPD_B + sOff[j], pBl + kh);                         \
        }                                                                      \
        asm volatile("cp.async.commit_group;");                                \
    } while (0)

    float acc[2][8][4];
#pragma unroll
    for (int i = 0; i < 2; ++i)
#pragma unroll
        for (int j = 0; j < 8; ++j)
#pragma unroll
            for (int k = 0; k < 4; ++k) acc[i][j][k] = 0.f;

    PREFETCH(0);

    const int aRowB = wm * 32 + (lane & 7) + ((lane >> 3) & 1) * 8;
    const int bRowB = wn * 64 + (lane & 7) + ((lane >> 4) & 1) * 8;
    const int aCsel = (lane >> 4) & 1;
    const int bCsel = (lane >> 3) & 1;

    for (int s = 0; s < NSTAGE; ++s) {
        if (s + 1 < NSTAGE) {
            PREFETCH(s + 1);
            asm volatile("cp.async.wait_group 1;");
        } else {
            asm volatile("cp.async.wait_group 0;");
        }
        __syncthreads();

        const uint32_t sa = sbase + (s & 1) * STAGE_B;
#pragma unroll
        for (int ks = 0; ks < 2; ++ks) {
            uint32_t aHi[2][4], aLo[2][4], bHi[8][2], bLo[8][2];
            const int cA = ks * 2 + aCsel;
            const int cB = ks * 2 + bCsel;
#pragma unroll
            for (int mt = 0; mt < 2; ++mt) {
                const int r_ = aRowB + mt * 16;
                const uint32_t off = r_ * 64 + ((cA ^ (r_ & 3)) << 4);
                ldsm4(aHi[mt], sa + off);
                ldsm4(aLo[mt], sa + OPD_B + off);
            }
#pragma unroll
            for (int p = 0; p < 4; ++p) {
                const int r_ = bRowB + p * 16;
                const uint32_t off = r_ * 64 + ((cB ^ (r_ & 3)) << 4);
                ldsm4(&bHi[2 * p][0], sa + 2 * OPD_B + off);
                ldsm4(&bLo[2 * p][0], sa + 3 * OPD_B + off);
            }
#pragma unroll
            for (int mt = 0; mt < 2; ++mt)
#pragma unroll
                for (int nt = 0; nt < 8; ++nt) {
                    mma16816(acc[mt][nt], aHi[mt], bHi[nt]);
                    mma16816(acc[mt][nt], aHi[mt], bLo[nt]);
                    mma16816(acc[mt][nt], aLo[mt], bHi[nt]);
                }
        }
        __syncthreads();
    }

    const int mBaseW = mTile + wm * 32 + (lane >> 2);
    const int nBaseW = nTile + wn * 64 + (lane & 3) * 2;
#pragma unroll
    for (int mt = 0; mt < 2; ++mt)
#pragma unroll
        for (int nt = 0; nt < 8; ++nt) {
            const int n = nBaseW + nt * 8;
            float b0 = 0.f, b1 = 0.f;
            if (mode != 1) {
                b0 = bias1[n] + bias2[n];
                b1 = bias1[n + 1] + bias2[n + 1];
            }
            const int m0 = mBaseW + mt * 16;
            float2 v0 = make_float2(acc[mt][nt][0] + b0, acc[mt][nt][1] + b1);
            float2 v1 = make_float2(acc[mt][nt][2] + b0, acc[mt][nt][3] + b1);
            *(float2*)(C + (size_t)m0 * N + n)       = v0;
            *(float2*)(C + (size_t)(m0 + 8) * N + n) = v1;
        }
#undef PREFETCH
}

// ---------------------------------------------------------------------------
// Flag grid barrier (unchanged, monotonic epochs)
// ---------------------------------------------------------------------------
#define GSYNC()                                                                  \
    do {                                                                         \
        __syncthreads();                                                         \
        ++nbar;                                                                  \
        const int target_ = s_base + nbar;                                       \
        if (tid == 0) {                                                          \
            __threadfence();                                                     \
            *((volatile int*)&g_arrive[blockIdx.x]) = target_;                   \
        }                                                                        \
        if (blockIdx.x == 0) {                                                   \
            if (tid < NBLK) {                                                    \
                while (*((volatile int*)&g_arrive[tid]) - target_ < 0) {}        \
            }                                                                    \
            __syncthreads();                                                     \
            if (tid == 0) {                                                      \
                __threadfence();                                                 \
                *((volatile int*)&g_release) = target_;                          \
            }                                                                    \
        } else if (tid == 0) {                                                   \
            while (*((volatile int*)&g_release) - target_ < 0) {}                \
            __threadfence();                                                     \
        }                                                                        \
        __syncthreads();                                                         \
    } while (0)

// ---------------------------------------------------------------------------
// One-layer recurrence pass, register-reuse matvec:
//   warp = K-chunk (32 warps x 32 k), lane = row (32 rows/CTA),
//   thread keeps all 8 batch accumulators in f32x2 registers.
//   w read 1x (lane-strided LDS.128, stride 1028 -> conflict-free),
//   h read via warp-broadcast LDS.128. K-split partials reduced in smem.
// ---------------------------------------------------------------------------
#define GPP 12      // padded partial row: [ks][r][GPP]
#define LSTMP_SMEM_FLOATS (32 * WP + 8 * HP + 32 * 32 * GPP + 256)
#define LSTMP_SMEM_BYTES  (LSTMP_SMEM_FLOATS * 4)

__global__ __launch_bounds__(1024, 1) void lstm_pass_kernel(
    const float* __restrict__ Wh, int layer, float* __restrict__ d_out) {
    extern __shared__ float smemf[];
    float* w0    = smemf;                             // 32 x WP
    float* hA    = smemf + 32 * WP;                   // 8 x HP
    float* gpart = smemf + 32 * WP + 8 * HP;          // 32 x 32 x GPP
    float* gsum  = gpart + 32 * 32 * GPP;             // 32 x 8

    const int tid  = threadIdx.x;
    const int ks   = tid >> 5;          // warp = K-chunk 0..31
    const int r    = tid & 31;          // lane = row 0..31 (gate*8 + unit)
    const int dl   = (tid < 64) ? (tid >> 3) : 0;   // cell-thread unit
    const int bb   = tid & 7;                       // cell-thread batch
    const int d    = (blockIdx.x << 3) + dl;

    const float* __restrict__ gx = layer ? g_Gx1 : g_Gx0;
    float* __restrict__ hseq     = layer ? g_lstm_out : g_h0seq;

    __shared__ int s_base;
    if (tid == 0) s_base = *((volatile int*)&g_release);

    // zero live hidden state (blocks 0..7)
    if (blockIdx.x < 8) g_h0[blockIdx.x * 1024 + tid] = 0.f;

    // cache this layer's Wh slice: row ru = gate*8 + unit_local
    for (int f = tid; f < 32 * 256; f += 1024) {
        const int ru = f >> 8;
        const int kf = f & 255;
        const int grow = layer * G4 + (ru >> 3) * 1024 + (blockIdx.x << 3) + (ru & 7);
        *(float4*)&w0[ru * WP + kf * 4] =
            *(const float4*)&Wh[(size_t)grow * DIM + kf * 4];
    }

    int nbar = 0;
    GSYNC();   // h zeroed + weights cached + s_base consistent

    const bool is_cell = (tid < 64);
    float c_l = 0.f, h_l = 0.f;

    const float* wr  = w0 + (size_t)r * WP + ks * 32;   // this thread's w chunk
    const float* hbb = hA + ks * 32;                    // + b*HP per batch
    float* gp = gpart + (ks * 32 + r) * GPP;

    for (int t = 0; t < SEQ; ++t) {
        // prefetch this step's x-path gate values (hidden under matvec)
        float gxv0 = 0.f, gxv1 = 0.f, gxv2 = 0.f, gxv3 = 0.f;
        if (is_cell) {
            const size_t ro = (size_t)((bb << 8) + t) * G4 + d;
            gxv0 = __ldcg(gx + ro);
            gxv1 = __ldcg(gx + ro + 1024);
            gxv2 = __ldcg(gx + ro + 2048);
            gxv3 = __ldcg(gx + ro + 3072);
        }

        // stage h_prev into smem [b][HP]
        for (int i = tid; i < 2048; i += 1024) {
            const float4 v = *(const float4*)(g_h0 + i * 4);
            *(float4*)&hA[(i >> 8) * HP + (i & 255) * 4] = v;
        }
        __syncthreads();

        // 32-k chunk x 8 batches, w 1x from smem, h broadcast, f32x2 FMA
        {
            unsigned long long acc2[8];
#pragma unroll
            for (int b = 0; b < 8; ++b) acc2[b] = 0ULL;
#pragma unroll
            for (int kk = 0; kk < 32; kk += 4) {
                const ulonglong2 wv = *(const ulonglong2*)(wr + kk);
#pragma unroll
                for (int b = 0; b < 8; ++b) {
                    const ulonglong2 hv = *(const ulonglong2*)(hbb + b * HP + kk);
                    ffma2(acc2[b], wv.x, hv.x);
                    ffma2(acc2[b], wv.y, hv.y);
                }
            }
            float s[8];
#pragma unroll
            for (int b = 0; b < 8; ++b) s[b] = f32x2_sum(acc2[b]);
            *(float4*)gp       = make_float4(s[0], s[1], s[2], s[3]);
            *(float4*)(gp + 4) = make_float4(s[4], s[5], s[6], s[7]);
        }
        __syncthreads();

        // reduce K-split partials: 256 threads, one (r,b) each
        if (tid < 256) {
            const int rr = tid >> 3, b2 = tid & 7;
            float s = 0.f;
#pragma unroll
            for (int k2 = 0; k2 < 32; ++k2)
                s += gpart[k2 * (32 * GPP) + rr * GPP + b2];
            gsum[tid] = s;
        }
        __syncthreads();

        if (is_cell) {
            const float gi = gsum[((0 << 3) + dl) * 8 + bb] + gxv0;
            const float gf = gsum[((1 << 3) + dl) * 8 + bb] + gxv1;
            const float go = gsum[((2 << 3) + dl) * 8 + bb] + gxv2;
            const float gg = gsum[((3 << 3) + dl) * 8 + bb] + gxv3;
            const float ct = sigf(gf) * c_l + sigf(gi) * tanhf(gg);
            const float ht = sigf(go) * tanhf(ct);
            c_l = ct; h_l = ht;
            g_h0[(bb << 10) + d] = ht;
            hseq[(size_t)((bb << 8) + t) * DIM + d] = ht;
        }
        GSYNC();
    }

    // finals: d_out = [logits | h_n(L,B,D) | c_n(L,B,D)]
    if (is_cell) {
        const size_t LOGN = (size_t)ROWS * VOCAB;
        d_out[LOGN + (size_t)layer * BATCH * DIM + (bb << 10) + d]                   = h_l;
        d_out[LOGN + 2 * BATCH * DIM + (size_t)layer * BATCH * DIM + (bb << 10) + d] = c_l;
    }
}

// ---------------------------------------------------------------------------
// RMSNorm (fp32)
// ---------------------------------------------------------------------------
__global__ __launch_bounds__(256) void rmsnorm_kernel(const float* __restrict__ w) {
    const int row = blockIdx.x, tid = threadIdx.x;
    const float4 v = *(((const float4*)(g_lstm_out + (size_t)row * DIM)) + tid);
    float ss = v.x * v.x + v.y * v.y + v.z * v.z + v.w * v.w;
#pragma unroll
    for (int o = 16; o; o >>= 1) ss += __shfl_xor_sync(0xffffffffu, ss, o);
    __shared__ float sred[8];
    __shared__ float sinv;
    if ((tid & 31) == 0) sred[tid >> 5] = ss;
    __syncthreads();
    if (tid == 0) {
        float tot = 0.f;
#pragma unroll
        for (int i = 0; i < 8; i++) tot += sred[i];
        sinv = rsqrtf(tot * (1.f / 1024.f) + 1e-5f);
    }
    __syncthreads();
    const float inv = sinv;
    const float4 wv = ((const float4*)w)[tid];
    float4 o4;
    o4.x = v.x * inv * wv.x;
    o4.y = v.y * inv * wv.y;
    o4.z = v.z * inv * wv.z;
    o4.w = v.w * inv * wv.w;
    *(((float4*)(g_normed + (size_t)row * DIM)) + tid) = o4;
}

// ---------------------------------------------------------------------------
// Launch — pass A at index 3 (ncu slot)
// ---------------------------------------------------------------------------
extern "C" void kernel_launch(void* const* d_in, const int* in_sizes, int n_in,
                              void* d_out, int out_size) {
    (void)in_sizes; (void)n_in; (void)out_size;
    const int*   ids  = (const int*)d_in[0];
    const float* emb  = (const float*)d_in[1];
    const float* Wx   = (const float*)d_in[2];
    const float* bx   = (const float*)d_in[3];
    const float* Wh   = (const float*)d_in[4];
    const float* bh   = (const float*)d_in[5];
    const float* nw   = (const float*)d_in[6];
    const float* Wout = (const float*)d_in[7];
    float* out = (float*)d_out;

    cudaFuncSetAttribute(lstm_pass_kernel, cudaFuncAttributeMaxDynamicSharedMemorySize,
                         LSTMP_SMEM_BYTES);
    cudaFuncSetAttribute(gemm3_mma, cudaFuncAttributeMaxDynamicSharedMemorySize,
                         GEMM_SMEM_BYTES);

    embed_split_kernel<<<ROWS, 256>>>(ids, emb);                            // 0
    convertW_kernel<<<4096, 256>>>(Wx, Wout);                               // 1
    gemm3_mma<<<dim3(ROWS / 128, G4 / 128), 256, GEMM_SMEM_BYTES>>>(        // 2
        0, bx, bh, out);
    lstm_pass_kernel<<<NBLK, 1024, LSTMP_SMEM_BYTES>>>(Wh, 0, out);         // 3 (ncu)
    conv_AhiAlo_kernel<<<2048, 256>>>(0);                                   // 4
    gemm3_mma<<<dim3(ROWS / 128, G4 / 128), 256, GEMM_SMEM_BYTES>>>(        // 5
        2, bx + G4, bh + G4, out);
    lstm_pass_kernel<<<NBLK, 1024, LSTMP_SMEM_BYTES>>>(Wh, 1, out);         // 6
    rmsnorm_kernel<<<ROWS, 256>>>(nw);                                      // 7
    conv_AhiAlo_kernel<<<2048, 256>>>(1);                                   // 8
    gemm3_mma<<<dim3(ROWS / 128, VOCAB / 128), 256, GEMM_SMEM_BYTES>>>(     // 9
        1, nullptr, nullptr, out);
}